// round 2
// baseline (speedup 1.0000x reference)
#include <cuda_runtime.h>
#include <math.h>
#include <stdint.h>

// Problem constants
#define BB 2
#define TT 1024
#define SSUP 8
#define LSUP 256
#define DD 1024
#define HH 16
#define DHH 64
#define KVL 2048              // S*L
#define MQ (BB*TT)            // 2048 query rows
#define MKV (BB*KVL)          // 4096 kv rows
#define KPAD 2056             // 2*D+3 padded to multiple of 8
#define KCAT (2*DD+3)         // 2051

// ---------------- scratch (static device memory; no allocations) -------------
__device__ float g_qin[MQ*DD];
__device__ float g_kvin[MKV*DD];
__device__ float g_q[MQ*DD];
__device__ float g_kv[MKV*2*DD];     // [:,0:1024]=k, [:,1024:2048]=v
__device__ float g_ctx[MQ*DD];
__device__ float g_attn[MQ*DD];
__device__ float g_gatein[MQ*KPAD];
__device__ float g_w1pad[DD*KPAD];
__device__ float g_h[MQ*DD];
__device__ float g_gate[MQ];

__device__ __forceinline__ float neg_inf() { return __int_as_float(0xff800000); }

__device__ __forceinline__ float gelu_exact(float x) {
    return 0.5f * x * (1.0f + erff(x * 0.70710678118654752f));
}

// ---------------- LayerNorm over rows of length 1024 -------------------------
__global__ void __launch_bounds__(256) ln_kernel(const float* __restrict__ x,
                                                 const float* __restrict__ w,
                                                 const float* __restrict__ b,
                                                 float* __restrict__ out) {
    int row = blockIdx.x;
    int tid = threadIdx.x;
    const float4* xr = (const float4*)(x + (size_t)row * DD);
    float4 v = xr[tid];
    float s  = v.x + v.y + v.z + v.w;
    float sq = v.x*v.x + v.y*v.y + v.z*v.z + v.w*v.w;
    #pragma unroll
    for (int o = 16; o > 0; o >>= 1) {
        s  += __shfl_xor_sync(0xffffffffu, s, o);
        sq += __shfl_xor_sync(0xffffffffu, sq, o);
    }
    __shared__ float rs[8], rq[8];
    int wid = tid >> 5, lid = tid & 31;
    if (lid == 0) { rs[wid] = s; rq[wid] = sq; }
    __syncthreads();
    s = 0.f; sq = 0.f;
    #pragma unroll
    for (int i = 0; i < 8; i++) { s += rs[i]; sq += rq[i]; }
    float mean = s * (1.0f / DD);
    float var  = sq * (1.0f / DD) - mean * mean;
    float rstd = rsqrtf(var + 1e-5f);
    float4 wv = ((const float4*)w)[tid];
    float4 bv = ((const float4*)b)[tid];
    float4 o4;
    o4.x = (v.x - mean) * rstd * wv.x + bv.x;
    o4.y = (v.y - mean) * rstd * wv.y + bv.y;
    o4.z = (v.z - mean) * rstd * wv.z + bv.z;
    o4.w = (v.w - mean) * rstd * wv.w + bv.w;
    ((float4*)(out + (size_t)row * DD))[tid] = o4;
}

// ---------------- SGEMM: C[M,N] = A[M,K] * W[N,K]^T + bias -------------------
// Requires M%128==0, N%128==0, K%8==0. EPI: 0 = none, 1 = exact GELU.
template<int EPI>
__global__ void __launch_bounds__(256, 2) sgemm_nt(const float* __restrict__ A,
                                                   const float* __restrict__ W,
                                                   const float* __restrict__ bias,
                                                   float* __restrict__ C,
                                                   int M, int N, int K) {
    __shared__ float As[8][128];
    __shared__ float Ws[8][128];
    int tid = threadIdx.x;
    int bm = blockIdx.y * 128, bn = blockIdx.x * 128;
    int lr = tid >> 1;
    int lc = (tid & 1) * 4;
    const float* Ap = A + (size_t)(bm + lr) * K + lc;
    const float* Wp = W + (size_t)(bn + lr) * K + lc;
    int tx = tid & 15, ty = tid >> 4;

    float acc[8][8];
    #pragma unroll
    for (int i = 0; i < 8; i++)
        #pragma unroll
        for (int j = 0; j < 8; j++) acc[i][j] = 0.f;

    for (int k0 = 0; k0 < K; k0 += 8) {
        float4 av = *(const float4*)(Ap + k0);
        float4 wv = *(const float4*)(Wp + k0);
        As[lc+0][lr] = av.x; As[lc+1][lr] = av.y; As[lc+2][lr] = av.z; As[lc+3][lr] = av.w;
        Ws[lc+0][lr] = wv.x; Ws[lc+1][lr] = wv.y; Ws[lc+2][lr] = wv.z; Ws[lc+3][lr] = wv.w;
        __syncthreads();
        #pragma unroll
        for (int kk = 0; kk < 8; kk++) {
            float4 a0 = *(const float4*)&As[kk][ty*8];
            float4 a1 = *(const float4*)&As[kk][ty*8+4];
            float4 b0 = *(const float4*)&Ws[kk][tx*8];
            float4 b1 = *(const float4*)&Ws[kk][tx*8+4];
            float a[8] = {a0.x,a0.y,a0.z,a0.w,a1.x,a1.y,a1.z,a1.w};
            float bb[8] = {b0.x,b0.y,b0.z,b0.w,b1.x,b1.y,b1.z,b1.w};
            #pragma unroll
            for (int i = 0; i < 8; i++)
                #pragma unroll
                for (int j = 0; j < 8; j++) acc[i][j] += a[i] * bb[j];
        }
        __syncthreads();
    }

    float4 bi0 = *(const float4*)(bias + bn + tx*8);
    float4 bi1 = *(const float4*)(bias + bn + tx*8 + 4);
    float bvals[8] = {bi0.x,bi0.y,bi0.z,bi0.w,bi1.x,bi1.y,bi1.z,bi1.w};
    #pragma unroll
    for (int i = 0; i < 8; i++) {
        size_t row = (size_t)(bm + ty*8 + i);
        float* crow = C + row * (size_t)N + bn + tx*8;
        float v[8];
        #pragma unroll
        for (int j = 0; j < 8; j++) {
            float t = acc[i][j] + bvals[j];
            if (EPI == 1) t = gelu_exact(t);
            v[j] = t;
        }
        ((float4*)crow)[0] = make_float4(v[0], v[1], v[2], v[3]);
        ((float4*)crow)[1] = make_float4(v[4], v[5], v[6], v[7]);
    }
}

// ---------------- fused flash attention (fp32) -------------------------------
// grid: (T/64, H, B). 256 threads. thread (r = tid>>2 query row, c4 = tid&3 owns
// kv/dh columns c4*16..c4*16+15). smem exactly 48KB: Qt + Kt(reused as P) + V.
// mask is int32: nonzero = valid token.
__global__ void __launch_bounds__(256, 2) attn_kernel(const float* __restrict__ Q,
                                                      const float* __restrict__ KVb,
                                                      const int* __restrict__ mask,
                                                      float* __restrict__ O) {
    __shared__ float Qts[64*64];   // [d][r]
    __shared__ float Kts[64*64];   // [d][kc]; reused as P: [kc][r]
    __shared__ float Vs[64*64];    // [kv][dcol]

    int tid = threadIdx.x;
    int r  = tid >> 2;
    int c4 = tid & 3;
    int b = blockIdx.z, h = blockIdx.y;
    int t0 = blockIdx.x * 64;

    // load Q tile transposed, pre-scaled by 1/sqrt(64)
    {
        const float4* qsrc = (const float4*)(Q + ((size_t)(b*TT + t0 + r)) * DD + h * DHH);
        #pragma unroll
        for (int u = 0; u < 4; u++) {
            float4 t = qsrc[c4 + 4*u];
            int d0 = (c4 + 4*u) * 4;
            Qts[(d0+0)*64 + r] = t.x * 0.125f;
            Qts[(d0+1)*64 + r] = t.y * 0.125f;
            Qts[(d0+2)*64 + r] = t.z * 0.125f;
            Qts[(d0+3)*64 + r] = t.w * 0.125f;
        }
    }

    float o[16];
    #pragma unroll
    for (int i = 0; i < 16; i++) o[i] = 0.f;
    float mrow = neg_inf();
    float lsum = 0.f;

    for (int kt = 0; kt < KVL/64; kt++) {
        __syncthreads();
        // load K tile (transposed) and V tile
        {
            const float* kb = KVb + ((size_t)(b*KVL + kt*64 + r)) * (2*DD) + h * DHH;
            const float4* ksrc = (const float4*)kb;
            const float4* vsrc = (const float4*)(kb + DD);
            #pragma unroll
            for (int u = 0; u < 4; u++) {
                float4 k4 = ksrc[c4 + 4*u];
                int d0 = (c4 + 4*u) * 4;
                Kts[(d0+0)*64 + r] = k4.x;
                Kts[(d0+1)*64 + r] = k4.y;
                Kts[(d0+2)*64 + r] = k4.z;
                Kts[(d0+3)*64 + r] = k4.w;
                ((float4*)&Vs[r*64])[c4 + 4*u] = vsrc[c4 + 4*u];
            }
        }
        // int32 mask for kv positions c4*16 .. c4*16+15 of this tile
        const int4* mp = (const int4*)(mask + (size_t)b*KVL + kt*64 + c4*16);
        int4 m0 = mp[0], m1 = mp[1], m2 = mp[2], m3 = mp[3];
        int mv[16] = {m0.x,m0.y,m0.z,m0.w, m1.x,m1.y,m1.z,m1.w,
                      m2.x,m2.y,m2.z,m2.w, m3.x,m3.y,m3.z,m3.w};
        __syncthreads();

        // S tile: s[j] = q_row . k_{c4*16+j}
        float s[16];
        #pragma unroll
        for (int j = 0; j < 16; j++) s[j] = 0.f;
        #pragma unroll 8
        for (int d = 0; d < 64; d++) {
            float qv = Qts[d*64 + r];
            const float4* kr = (const float4*)&Kts[d*64 + c4*16];
            float4 k0 = kr[0], k1 = kr[1], k2 = kr[2], k3 = kr[3];
            s[0]  += qv*k0.x; s[1]  += qv*k0.y; s[2]  += qv*k0.z; s[3]  += qv*k0.w;
            s[4]  += qv*k1.x; s[5]  += qv*k1.y; s[6]  += qv*k1.z; s[7]  += qv*k1.w;
            s[8]  += qv*k2.x; s[9]  += qv*k2.y; s[10] += qv*k2.z; s[11] += qv*k2.w;
            s[12] += qv*k3.x; s[13] += qv*k3.y; s[14] += qv*k3.z; s[15] += qv*k3.w;
        }
        // mask (0 -> -inf)
        #pragma unroll
        for (int j = 0; j < 16; j++) {
            if (mv[j] == 0) s[j] = neg_inf();
        }
        // online softmax
        float tmax = s[0];
        #pragma unroll
        for (int j = 1; j < 16; j++) tmax = fmaxf(tmax, s[j]);
        tmax = fmaxf(tmax, __shfl_xor_sync(0xffffffffu, tmax, 1));
        tmax = fmaxf(tmax, __shfl_xor_sync(0xffffffffu, tmax, 2));
        float mnew  = fmaxf(mrow, tmax);
        float mbase = fmaxf(mnew, -1e30f);
        float corr  = __expf(mrow - mbase);
        float p[16];
        float tsum = 0.f;
        #pragma unroll
        for (int j = 0; j < 16; j++) { p[j] = __expf(s[j] - mbase); tsum += p[j]; }
        tsum += __shfl_xor_sync(0xffffffffu, tsum, 1);
        tsum += __shfl_xor_sync(0xffffffffu, tsum, 2);
        lsum = lsum * corr + tsum;
        mrow = mnew;
        #pragma unroll
        for (int i = 0; i < 16; i++) o[i] *= corr;

        __syncthreads();
        #pragma unroll
        for (int j = 0; j < 16; j++) Kts[(c4*16 + j)*64 + r] = p[j];
        __syncthreads();

        // O += P @ V
        #pragma unroll 8
        for (int k = 0; k < 64; k++) {
            float pv = Kts[k*64 + r];
            const float4* vr = (const float4*)&Vs[k*64 + c4*16];
            float4 v0 = vr[0], v1 = vr[1], v2 = vr[2], v3 = vr[3];
            o[0]  += pv*v0.x; o[1]  += pv*v0.y; o[2]  += pv*v0.z; o[3]  += pv*v0.w;
            o[4]  += pv*v1.x; o[5]  += pv*v1.y; o[6]  += pv*v1.z; o[7]  += pv*v1.w;
            o[8]  += pv*v2.x; o[9]  += pv*v2.y; o[10] += pv*v2.z; o[11] += pv*v2.w;
            o[12] += pv*v3.x; o[13] += pv*v3.y; o[14] += pv*v3.z; o[15] += pv*v3.w;
        }
    }

    float inv = 1.f / lsum;
    float4* orow = (float4*)(O + ((size_t)(b*TT + t0 + r)) * DD + h * DHH + c4*16);
    orow[0] = make_float4(o[0]*inv,  o[1]*inv,  o[2]*inv,  o[3]*inv);
    orow[1] = make_float4(o[4]*inv,  o[5]*inv,  o[6]*inv,  o[7]*inv);
    orow[2] = make_float4(o[8]*inv,  o[9]*inv,  o[10]*inv, o[11]*inv);
    orow[3] = make_float4(o[12]*inv, o[13]*inv, o[14]*inv, o[15]*inv);
}

// ---------------- pack kernels -----------------------------------------------
__global__ void pack_gatein(const float* __restrict__ target,
                            const float* __restrict__ attn,
                            const float* __restrict__ feat,
                            float* __restrict__ out) {
    int idx = blockIdx.x * blockDim.x + threadIdx.x;
    if (idx >= MQ * KPAD) return;
    int m = idx / KPAD, j = idx % KPAD;
    float v;
    if (j < DD)            v = target[(size_t)m*DD + j];
    else if (j < 2*DD)     v = attn[(size_t)m*DD + (j - DD)];
    else if (j < KCAT)     v = feat[(size_t)m*3 + (j - 2*DD)];
    else                   v = 0.f;
    out[idx] = v;
}

__global__ void pack_w1(const float* __restrict__ w1, float* __restrict__ out) {
    int idx = blockIdx.x * blockDim.x + threadIdx.x;
    if (idx >= DD * KPAD) return;
    int n = idx / KPAD, j = idx % KPAD;
    out[idx] = (j < KCAT) ? w1[(size_t)n*KCAT + j] : 0.f;
}

// ---------------- gate = sigmoid(h . w2 + b2) ---------------------------------
__global__ void __launch_bounds__(256) gate2_kernel(const float* __restrict__ hbuf,
                                                    const float* __restrict__ w2,
                                                    const float* __restrict__ b2,
                                                    float* __restrict__ gate) {
    int row = blockIdx.x;
    int tid = threadIdx.x;
    float4 hv = ((const float4*)(hbuf + (size_t)row * DD))[tid];
    float4 wv = ((const float4*)w2)[tid];
    float s = hv.x*wv.x + hv.y*wv.y + hv.z*wv.z + hv.w*wv.w;
    #pragma unroll
    for (int o = 16; o > 0; o >>= 1) s += __shfl_xor_sync(0xffffffffu, s, o);
    __shared__ float rs[8];
    int wid = tid >> 5, lid = tid & 31;
    if (lid == 0) rs[wid] = s;
    __syncthreads();
    if (tid == 0) {
        float tot = 0.f;
        #pragma unroll
        for (int i = 0; i < 8; i++) tot += rs[i];
        gate[row] = 1.f / (1.f + __expf(-(tot + b2[0])));
    }
}

// ---------------- fuse + residual + output LN --------------------------------
__global__ void __launch_bounds__(256) final_kernel(const float* __restrict__ target,
                                                    const float* __restrict__ attn,
                                                    const float* __restrict__ gate,
                                                    const float* __restrict__ w,
                                                    const float* __restrict__ bparm,
                                                    float* __restrict__ out,
                                                    float* __restrict__ gate_out) {
    int row = blockIdx.x;
    int tid = threadIdx.x;
    float g = gate[row];
    float4 t4 = ((const float4*)(target + (size_t)row * DD))[tid];
    float4 a4 = ((const float4*)(attn   + (size_t)row * DD))[tid];
    // x = target + (g*attn + (1-g)*target) = (2-g)*target + g*attn
    float4 x;
    x.x = (2.f - g)*t4.x + g*a4.x;
    x.y = (2.f - g)*t4.y + g*a4.y;
    x.z = (2.f - g)*t4.z + g*a4.z;
    x.w = (2.f - g)*t4.w + g*a4.w;
    float s  = x.x + x.y + x.z + x.w;
    float sq = x.x*x.x + x.y*x.y + x.z*x.z + x.w*x.w;
    #pragma unroll
    for (int o = 16; o > 0; o >>= 1) {
        s  += __shfl_xor_sync(0xffffffffu, s, o);
        sq += __shfl_xor_sync(0xffffffffu, sq, o);
    }
    __shared__ float rs[8], rq[8];
    int wid = tid >> 5, lid = tid & 31;
    if (lid == 0) { rs[wid] = s; rq[wid] = sq; }
    __syncthreads();
    s = 0.f; sq = 0.f;
    #pragma unroll
    for (int i = 0; i < 8; i++) { s += rs[i]; sq += rq[i]; }
    float mean = s * (1.0f / DD);
    float var  = sq * (1.0f / DD) - mean * mean;
    float rstd = rsqrtf(var + 1e-5f);
    float4 wv = ((const float4*)w)[tid];
    float4 bv = ((const float4*)bparm)[tid];
    float4 o4;
    o4.x = (x.x - mean)*rstd*wv.x + bv.x;
    o4.y = (x.y - mean)*rstd*wv.y + bv.y;
    o4.z = (x.z - mean)*rstd*wv.z + bv.z;
    o4.w = (x.w - mean)*rstd*wv.w + bv.w;
    ((float4*)(out + (size_t)row * DD))[tid] = o4;
    if (gate_out && tid == 0) gate_out[row] = g;
}

// ---------------- launch ------------------------------------------------------
extern "C" void kernel_launch(void* const* d_in, const int* in_sizes, int n_in,
                              void* d_out, int out_size) {
    const float* target   = (const float*)d_in[0];
    const float* support  = (const float*)d_in[1];
    const float* feat     = (const float*)d_in[2];
    const int*   mask     = (const int*)d_in[3];
    const float* ln_q_w   = (const float*)d_in[4];
    const float* ln_q_b   = (const float*)d_in[5];
    const float* ln_kv_w  = (const float*)d_in[6];
    const float* ln_kv_b  = (const float*)d_in[7];
    const float* out_ln_w = (const float*)d_in[8];
    const float* out_ln_b = (const float*)d_in[9];
    const float* in_proj_w  = (const float*)d_in[10];
    const float* in_proj_b  = (const float*)d_in[11];
    const float* out_proj_w = (const float*)d_in[12];
    const float* out_proj_b = (const float*)d_in[13];
    const float* gate_w1 = (const float*)d_in[14];
    const float* gate_b1 = (const float*)d_in[15];
    const float* gate_w2 = (const float*)d_in[16];
    const float* gate_b2 = (const float*)d_in[17];

    float *qin, *kvin, *q, *kv, *ctx, *attn, *gatein, *w1p, *hbuf, *gate;
    cudaGetSymbolAddress((void**)&qin,    g_qin);
    cudaGetSymbolAddress((void**)&kvin,   g_kvin);
    cudaGetSymbolAddress((void**)&q,      g_q);
    cudaGetSymbolAddress((void**)&kv,     g_kv);
    cudaGetSymbolAddress((void**)&ctx,    g_ctx);
    cudaGetSymbolAddress((void**)&attn,   g_attn);
    cudaGetSymbolAddress((void**)&gatein, g_gatein);
    cudaGetSymbolAddress((void**)&w1p,    g_w1pad);
    cudaGetSymbolAddress((void**)&hbuf,   g_h);
    cudaGetSymbolAddress((void**)&gate,   g_gate);

    // 1. input layernorms
    ln_kernel<<<MQ, 256>>>(target, ln_q_w, ln_q_b, qin);
    ln_kernel<<<MKV, 256>>>(support, ln_kv_w, ln_kv_b, kvin);

    // 2. projections (q, fused kv)
    sgemm_nt<0><<<dim3(DD/128, MQ/128), 256>>>(qin, in_proj_w, in_proj_b, q, MQ, DD, DD);
    sgemm_nt<0><<<dim3((2*DD)/128, MKV/128), 256>>>(kvin, in_proj_w + (size_t)DD*DD,
                                                    in_proj_b + DD, kv, MKV, 2*DD, DD);

    // 3. attention
    attn_kernel<<<dim3(TT/64, HH, BB), 256>>>(q, kv, mask, ctx);

    // 4. output projection
    sgemm_nt<0><<<dim3(DD/128, MQ/128), 256>>>(ctx, out_proj_w, out_proj_b, attn, MQ, DD, DD);

    // 5. gate MLP
    pack_w1<<<(DD*KPAD + 255)/256, 256>>>(gate_w1, w1p);
    pack_gatein<<<(MQ*KPAD + 255)/256, 256>>>(target, attn, feat, gatein);
    sgemm_nt<1><<<dim3(DD/128, MQ/128), 256>>>(gatein, w1p, gate_b1, hbuf, MQ, DD, KPAD);
    gate2_kernel<<<MQ, 256>>>(hbuf, gate_w2, gate_b2, gate);

    // 6. fuse + residual + output LN (+ gate second output)
    float* gout = nullptr;
    if (out_size >= MQ*DD + MQ) gout = (float*)d_out + (size_t)MQ*DD;
    final_kernel<<<MQ, 256>>>(target, attn, gate, out_ln_w, out_ln_b, (float*)d_out, gout);
}

// round 3
// speedup vs baseline: 1.2116x; 1.2116x over previous
#include <cuda_runtime.h>
#include <math.h>
#include <stdint.h>

// Problem constants
#define BB 2
#define TT 1024
#define DD 1024
#define HH 16
#define DHH 64
#define KVL 2048              // S*L
#define MQ (BB*TT)            // 2048 query rows
#define MKV (BB*KVL)          // 4096 kv rows
#define KPAD 2080             // 2*D+3 padded to multiple of 32
#define KCAT (2*DD+3)         // 2051

// ---------------- scratch (static device memory; no allocations) -------------
__device__ float g_qin[MQ*DD];
__device__ float g_kvin[MKV*DD];
__device__ float g_q[MQ*DD];
__device__ float g_kv[MKV*2*DD];     // [:,0:1024]=k, [:,1024:2048]=v
__device__ float g_ctx[MQ*DD];
__device__ float g_attn[MQ*DD];
__device__ float g_gatein[MQ*KPAD];
__device__ float g_w1pad[DD*KPAD];
__device__ float g_h[MQ*DD];
__device__ float g_gate[MQ];

__device__ __forceinline__ float neg_inf() { return __int_as_float(0xff800000); }

__device__ __forceinline__ float gelu_exact(float x) {
    return 0.5f * x * (1.0f + erff(x * 0.70710678118654752f));
}

__device__ __forceinline__ uint32_t tf32r(float x) {
    uint32_t o;
    asm("cvt.rna.tf32.f32 %0, %1;" : "=r"(o) : "f"(x));
    return o;
}

__device__ __forceinline__ void mma_tf32(float* c, const uint32_t* a, const uint32_t* b) {
    asm volatile(
        "mma.sync.aligned.m16n8k8.row.col.f32.tf32.tf32.f32 "
        "{%0,%1,%2,%3}, {%4,%5,%6,%7}, {%8,%9}, {%0,%1,%2,%3};"
        : "+f"(c[0]), "+f"(c[1]), "+f"(c[2]), "+f"(c[3])
        : "r"(a[0]), "r"(a[1]), "r"(a[2]), "r"(a[3]), "r"(b[0]), "r"(b[1]));
}

// ---------------- LayerNorm over rows of length 1024 -------------------------
__global__ void __launch_bounds__(256) ln_kernel(const float* __restrict__ x,
                                                 const float* __restrict__ w,
                                                 const float* __restrict__ b,
                                                 float* __restrict__ out) {
    int row = blockIdx.x;
    int tid = threadIdx.x;
    const float4* xr = (const float4*)(x + (size_t)row * DD);
    float4 v = xr[tid];
    float s  = v.x + v.y + v.z + v.w;
    float sq = v.x*v.x + v.y*v.y + v.z*v.z + v.w*v.w;
    #pragma unroll
    for (int o = 16; o > 0; o >>= 1) {
        s  += __shfl_xor_sync(0xffffffffu, s, o);
        sq += __shfl_xor_sync(0xffffffffu, sq, o);
    }
    __shared__ float rs[8], rq[8];
    int wid = tid >> 5, lid = tid & 31;
    if (lid == 0) { rs[wid] = s; rq[wid] = sq; }
    __syncthreads();
    s = 0.f; sq = 0.f;
    #pragma unroll
    for (int i = 0; i < 8; i++) { s += rs[i]; sq += rq[i]; }
    float mean = s * (1.0f / DD);
    float var  = sq * (1.0f / DD) - mean * mean;
    float rstd = rsqrtf(var + 1e-5f);
    float4 wv = ((const float4*)w)[tid];
    float4 bv = ((const float4*)b)[tid];
    float4 o4;
    o4.x = (v.x - mean) * rstd * wv.x + bv.x;
    o4.y = (v.y - mean) * rstd * wv.y + bv.y;
    o4.z = (v.z - mean) * rstd * wv.z + bv.z;
    o4.w = (v.w - mean) * rstd * wv.w + bv.w;
    ((float4*)(out + (size_t)row * DD))[tid] = o4;
}

// ---------------- tf32 tensor-core GEMM: C[M,N] = A[M,K] * W[N,K]^T + bias ---
// Block 128x128x32, 256 threads = 8 warps (4x2), warp tile 32x64 (2x8 mma tiles).
// Requires M%128==0, N%128==0, K%32==0. EPI: 0 = none, 1 = exact GELU.
template<int EPI>
__global__ void __launch_bounds__(256, 2) gemm_tf32(const float* __restrict__ A,
                                                    const float* __restrict__ W,
                                                    const float* __restrict__ bias,
                                                    float* __restrict__ C,
                                                    int M, int N, int K) {
    __shared__ float As[32][132];   // [k][m], padded
    __shared__ float Ws[32][132];   // [k][n], padded

    int tid  = threadIdx.x;
    int lane = tid & 31;
    int warp = tid >> 5;
    int wm = (warp & 3) * 32;       // warp row base within block
    int wn = (warp >> 2) * 64;      // warp col base within block
    int bm = blockIdx.y * 128, bn = blockIdx.x * 128;

    int lrow = tid >> 3;            // 0..31 row within 32-row chunk
    int lcol = (tid & 7) * 4;       // k offset 0..28

    int qr = lane >> 2;             // 0..7
    int qc = lane & 3;              // 0..3

    float acc[2][8][4];
    #pragma unroll
    for (int i = 0; i < 2; i++)
        #pragma unroll
        for (int j = 0; j < 8; j++)
            #pragma unroll
            for (int t = 0; t < 4; t++) acc[i][j][t] = 0.f;

    for (int k0 = 0; k0 < K; k0 += 32) {
        #pragma unroll
        for (int u = 0; u < 4; u++) {
            int r = u * 32 + lrow;
            float4 av = *(const float4*)(A + (size_t)(bm + r) * K + k0 + lcol);
            float4 wv = *(const float4*)(W + (size_t)(bn + r) * K + k0 + lcol);
            As[lcol+0][r] = av.x; As[lcol+1][r] = av.y;
            As[lcol+2][r] = av.z; As[lcol+3][r] = av.w;
            Ws[lcol+0][r] = wv.x; Ws[lcol+1][r] = wv.y;
            Ws[lcol+2][r] = wv.z; Ws[lcol+3][r] = wv.w;
        }
        __syncthreads();

        #pragma unroll
        for (int kk = 0; kk < 4; kk++) {
            int kb = kk * 8;
            uint32_t af[2][4];
            #pragma unroll
            for (int mt = 0; mt < 2; mt++) {
                int mb = wm + mt * 16;
                af[mt][0] = tf32r(As[kb + qc    ][mb + qr    ]);
                af[mt][1] = tf32r(As[kb + qc    ][mb + qr + 8]);
                af[mt][2] = tf32r(As[kb + qc + 4][mb + qr    ]);
                af[mt][3] = tf32r(As[kb + qc + 4][mb + qr + 8]);
            }
            uint32_t bf[8][2];
            #pragma unroll
            for (int nt = 0; nt < 8; nt++) {
                int nb = wn + nt * 8;
                bf[nt][0] = tf32r(Ws[kb + qc    ][nb + qr]);
                bf[nt][1] = tf32r(Ws[kb + qc + 4][nb + qr]);
            }
            #pragma unroll
            for (int mt = 0; mt < 2; mt++)
                #pragma unroll
                for (int nt = 0; nt < 8; nt++)
                    mma_tf32(acc[mt][nt], af[mt], bf[nt]);
        }
        __syncthreads();
    }

    // Epilogue: c0 -> (row, col), c1 -> (row, col+1), c2/c3 -> row+8
    #pragma unroll
    for (int mt = 0; mt < 2; mt++) {
        int row0 = bm + wm + mt * 16 + qr;
        #pragma unroll
        for (int nt = 0; nt < 8; nt++) {
            int col = bn + wn + nt * 8 + qc * 2;
            float2 bi = *(const float2*)(bias + col);
            float v0 = acc[mt][nt][0] + bi.x;
            float v1 = acc[mt][nt][1] + bi.y;
            float v2 = acc[mt][nt][2] + bi.x;
            float v3 = acc[mt][nt][3] + bi.y;
            if (EPI == 1) {
                v0 = gelu_exact(v0); v1 = gelu_exact(v1);
                v2 = gelu_exact(v2); v3 = gelu_exact(v3);
            }
            *(float2*)(C + (size_t)row0 * N + col)       = make_float2(v0, v1);
            *(float2*)(C + (size_t)(row0 + 8) * N + col) = make_float2(v2, v3);
        }
    }
}

// ---------------- fused flash attention (fp32) -------------------------------
// grid: (T/64, H, B). 256 threads. mask is int32: nonzero = valid token.
__global__ void __launch_bounds__(256, 2) attn_kernel(const float* __restrict__ Q,
                                                      const float* __restrict__ KVb,
                                                      const int* __restrict__ mask,
                                                      float* __restrict__ O) {
    __shared__ float Qts[64*64];   // [d][r]
    __shared__ float Kts[64*64];   // [d][kc]; reused as P: [kc][r]
    __shared__ float Vs[64*64];    // [kv][dcol]

    int tid = threadIdx.x;
    int r  = tid >> 2;
    int c4 = tid & 3;
    int b = blockIdx.z, h = blockIdx.y;
    int t0 = blockIdx.x * 64;

    {
        const float4* qsrc = (const float4*)(Q + ((size_t)(b*TT + t0 + r)) * DD + h * DHH);
        #pragma unroll
        for (int u = 0; u < 4; u++) {
            float4 t = qsrc[c4 + 4*u];
            int d0 = (c4 + 4*u) * 4;
            Qts[(d0+0)*64 + r] = t.x * 0.125f;
            Qts[(d0+1)*64 + r] = t.y * 0.125f;
            Qts[(d0+2)*64 + r] = t.z * 0.125f;
            Qts[(d0+3)*64 + r] = t.w * 0.125f;
        }
    }

    float o[16];
    #pragma unroll
    for (int i = 0; i < 16; i++) o[i] = 0.f;
    float mrow = neg_inf();
    float lsum = 0.f;

    for (int kt = 0; kt < KVL/64; kt++) {
        __syncthreads();
        {
            const float* kb = KVb + ((size_t)(b*KVL + kt*64 + r)) * (2*DD) + h * DHH;
            const float4* ksrc = (const float4*)kb;
            const float4* vsrc = (const float4*)(kb + DD);
            #pragma unroll
            for (int u = 0; u < 4; u++) {
                float4 k4 = ksrc[c4 + 4*u];
                int d0 = (c4 + 4*u) * 4;
                Kts[(d0+0)*64 + r] = k4.x;
                Kts[(d0+1)*64 + r] = k4.y;
                Kts[(d0+2)*64 + r] = k4.z;
                Kts[(d0+3)*64 + r] = k4.w;
                ((float4*)&Vs[r*64])[c4 + 4*u] = vsrc[c4 + 4*u];
            }
        }
        const int4* mp = (const int4*)(mask + (size_t)b*KVL + kt*64 + c4*16);
        int4 m0 = mp[0], m1 = mp[1], m2 = mp[2], m3 = mp[3];
        int mv[16] = {m0.x,m0.y,m0.z,m0.w, m1.x,m1.y,m1.z,m1.w,
                      m2.x,m2.y,m2.z,m2.w, m3.x,m3.y,m3.z,m3.w};
        __syncthreads();

        float s[16];
        #pragma unroll
        for (int j = 0; j < 16; j++) s[j] = 0.f;
        #pragma unroll 8
        for (int d = 0; d < 64; d++) {
            float qv = Qts[d*64 + r];
            const float4* kr = (const float4*)&Kts[d*64 + c4*16];
            float4 k0 = kr[0], k1 = kr[1], k2 = kr[2], k3 = kr[3];
            s[0]  += qv*k0.x; s[1]  += qv*k0.y; s[2]  += qv*k0.z; s[3]  += qv*k0.w;
            s[4]  += qv*k1.x; s[5]  += qv*k1.y; s[6]  += qv*k1.z; s[7]  += qv*k1.w;
            s[8]  += qv*k2.x; s[9]  += qv*k2.y; s[10] += qv*k2.z; s[11] += qv*k2.w;
            s[12] += qv*k3.x; s[13] += qv*k3.y; s[14] += qv*k3.z; s[15] += qv*k3.w;
        }
        #pragma unroll
        for (int j = 0; j < 16; j++) {
            if (mv[j] == 0) s[j] = neg_inf();
        }
        float tmax = s[0];
        #pragma unroll
        for (int j = 1; j < 16; j++) tmax = fmaxf(tmax, s[j]);
        tmax = fmaxf(tmax, __shfl_xor_sync(0xffffffffu, tmax, 1));
        tmax = fmaxf(tmax, __shfl_xor_sync(0xffffffffu, tmax, 2));
        float mnew  = fmaxf(mrow, tmax);
        float mbase = fmaxf(mnew, -1e30f);
        float corr  = __expf(mrow - mbase);
        float p[16];
        float tsum = 0.f;
        #pragma unroll
        for (int j = 0; j < 16; j++) { p[j] = __expf(s[j] - mbase); tsum += p[j]; }
        tsum += __shfl_xor_sync(0xffffffffu, tsum, 1);
        tsum += __shfl_xor_sync(0xffffffffu, tsum, 2);
        lsum = lsum * corr + tsum;
        mrow = mnew;
        #pragma unroll
        for (int i = 0; i < 16; i++) o[i] *= corr;

        __syncthreads();
        #pragma unroll
        for (int j = 0; j < 16; j++) Kts[(c4*16 + j)*64 + r] = p[j];
        __syncthreads();

        #pragma unroll 8
        for (int k = 0; k < 64; k++) {
            float pv = Kts[k*64 + r];
            const float4* vr = (const float4*)&Vs[k*64 + c4*16];
            float4 v0 = vr[0], v1 = vr[1], v2 = vr[2], v3 = vr[3];
            o[0]  += pv*v0.x; o[1]  += pv*v0.y; o[2]  += pv*v0.z; o[3]  += pv*v0.w;
            o[4]  += pv*v1.x; o[5]  += pv*v1.y; o[6]  += pv*v1.z; o[7]  += pv*v1.w;
            o[8]  += pv*v2.x; o[9]  += pv*v2.y; o[10] += pv*v2.z; o[11] += pv*v2.w;
            o[12] += pv*v3.x; o[13] += pv*v3.y; o[14] += pv*v3.z; o[15] += pv*v3.w;
        }
    }

    float inv = 1.f / lsum;
    float4* orow = (float4*)(O + ((size_t)(b*TT + t0 + r)) * DD + h * DHH + c4*16);
    orow[0] = make_float4(o[0]*inv,  o[1]*inv,  o[2]*inv,  o[3]*inv);
    orow[1] = make_float4(o[4]*inv,  o[5]*inv,  o[6]*inv,  o[7]*inv);
    orow[2] = make_float4(o[8]*inv,  o[9]*inv,  o[10]*inv, o[11]*inv);
    orow[3] = make_float4(o[12]*inv, o[13]*inv, o[14]*inv, o[15]*inv);
}

// ---------------- pack kernels -----------------------------------------------
__global__ void pack_gatein(const float* __restrict__ target,
                            const float* __restrict__ attn,
                            const float* __restrict__ feat,
                            float* __restrict__ out) {
    int idx = blockIdx.x * blockDim.x + threadIdx.x;
    if (idx >= MQ * KPAD) return;
    int m = idx / KPAD, j = idx % KPAD;
    float v;
    if (j < DD)            v = target[(size_t)m*DD + j];
    else if (j < 2*DD)     v = attn[(size_t)m*DD + (j - DD)];
    else if (j < KCAT)     v = feat[(size_t)m*3 + (j - 2*DD)];
    else                   v = 0.f;
    out[idx] = v;
}

__global__ void pack_w1(const float* __restrict__ w1, float* __restrict__ out) {
    int idx = blockIdx.x * blockDim.x + threadIdx.x;
    if (idx >= DD * KPAD) return;
    int n = idx / KPAD, j = idx % KPAD;
    out[idx] = (j < KCAT) ? w1[(size_t)n*KCAT + j] : 0.f;
}

// ---------------- gate = sigmoid(h . w2 + b2) ---------------------------------
__global__ void __launch_bounds__(256) gate2_kernel(const float* __restrict__ hbuf,
                                                    const float* __restrict__ w2,
                                                    const float* __restrict__ b2,
                                                    float* __restrict__ gate) {
    int row = blockIdx.x;
    int tid = threadIdx.x;
    float4 hv = ((const float4*)(hbuf + (size_t)row * DD))[tid];
    float4 wv = ((const float4*)w2)[tid];
    float s = hv.x*wv.x + hv.y*wv.y + hv.z*wv.z + hv.w*wv.w;
    #pragma unroll
    for (int o = 16; o > 0; o >>= 1) s += __shfl_xor_sync(0xffffffffu, s, o);
    __shared__ float rs[8];
    int wid = tid >> 5, lid = tid & 31;
    if (lid == 0) rs[wid] = s;
    __syncthreads();
    if (tid == 0) {
        float tot = 0.f;
        #pragma unroll
        for (int i = 0; i < 8; i++) tot += rs[i];
        gate[row] = 1.f / (1.f + __expf(-(tot + b2[0])));
    }
}

// ---------------- fuse + residual + output LN --------------------------------
__global__ void __launch_bounds__(256) final_kernel(const float* __restrict__ target,
                                                    const float* __restrict__ attn,
                                                    const float* __restrict__ gate,
                                                    const float* __restrict__ w,
                                                    const float* __restrict__ bparm,
                                                    float* __restrict__ out,
                                                    float* __restrict__ gate_out) {
    int row = blockIdx.x;
    int tid = threadIdx.x;
    float g = gate[row];
    float4 t4 = ((const float4*)(target + (size_t)row * DD))[tid];
    float4 a4 = ((const float4*)(attn   + (size_t)row * DD))[tid];
    float4 x;
    x.x = (2.f - g)*t4.x + g*a4.x;
    x.y = (2.f - g)*t4.y + g*a4.y;
    x.z = (2.f - g)*t4.z + g*a4.z;
    x.w = (2.f - g)*t4.w + g*a4.w;
    float s  = x.x + x.y + x.z + x.w;
    float sq = x.x*x.x + x.y*x.y + x.z*x.z + x.w*x.w;
    #pragma unroll
    for (int o = 16; o > 0; o >>= 1) {
        s  += __shfl_xor_sync(0xffffffffu, s, o);
        sq += __shfl_xor_sync(0xffffffffu, sq, o);
    }
    __shared__ float rs[8], rq[8];
    int wid = tid >> 5, lid = tid & 31;
    if (lid == 0) { rs[wid] = s; rq[wid] = sq; }
    __syncthreads();
    s = 0.f; sq = 0.f;
    #pragma unroll
    for (int i = 0; i < 8; i++) { s += rs[i]; sq += rq[i]; }
    float mean = s * (1.0f / DD);
    float var  = sq * (1.0f / DD) - mean * mean;
    float rstd = rsqrtf(var + 1e-5f);
    float4 wv = ((const float4*)w)[tid];
    float4 bv = ((const float4*)bparm)[tid];
    float4 o4;
    o4.x = (x.x - mean)*rstd*wv.x + bv.x;
    o4.y = (x.y - mean)*rstd*wv.y + bv.y;
    o4.z = (x.z - mean)*rstd*wv.z + bv.z;
    o4.w = (x.w - mean)*rstd*wv.w + bv.w;
    ((float4*)(out + (size_t)row * DD))[tid] = o4;
    if (gate_out && tid == 0) gate_out[row] = g;
}

// ---------------- launch ------------------------------------------------------
extern "C" void kernel_launch(void* const* d_in, const int* in_sizes, int n_in,
                              void* d_out, int out_size) {
    const float* target   = (const float*)d_in[0];
    const float* support  = (const float*)d_in[1];
    const float* feat     = (const float*)d_in[2];
    const int*   mask     = (const int*)d_in[3];
    const float* ln_q_w   = (const float*)d_in[4];
    const float* ln_q_b   = (const float*)d_in[5];
    const float* ln_kv_w  = (const float*)d_in[6];
    const float* ln_kv_b  = (const float*)d_in[7];
    const float* out_ln_w = (const float*)d_in[8];
    const float* out_ln_b = (const float*)d_in[9];
    const float* in_proj_w  = (const float*)d_in[10];
    const float* in_proj_b  = (const float*)d_in[11];
    const float* out_proj_w = (const float*)d_in[12];
    const float* out_proj_b = (const float*)d_in[13];
    const float* gate_w1 = (const float*)d_in[14];
    const float* gate_b1 = (const float*)d_in[15];
    const float* gate_w2 = (const float*)d_in[16];
    const float* gate_b2 = (const float*)d_in[17];

    float *qin, *kvin, *q, *kv, *ctx, *attn, *gatein, *w1p, *hbuf, *gate;
    cudaGetSymbolAddress((void**)&qin,    g_qin);
    cudaGetSymbolAddress((void**)&kvin,   g_kvin);
    cudaGetSymbolAddress((void**)&q,      g_q);
    cudaGetSymbolAddress((void**)&kv,     g_kv);
    cudaGetSymbolAddress((void**)&ctx,    g_ctx);
    cudaGetSymbolAddress((void**)&attn,   g_attn);
    cudaGetSymbolAddress((void**)&gatein, g_gatein);
    cudaGetSymbolAddress((void**)&w1p,    g_w1pad);
    cudaGetSymbolAddress((void**)&hbuf,   g_h);
    cudaGetSymbolAddress((void**)&gate,   g_gate);

    // 1. input layernorms
    ln_kernel<<<MQ, 256>>>(target, ln_q_w, ln_q_b, qin);
    ln_kernel<<<MKV, 256>>>(support, ln_kv_w, ln_kv_b, kvin);

    // 2. projections (q, fused kv) — tf32 tensor cores
    gemm_tf32<0><<<dim3(DD/128, MQ/128), 256>>>(qin, in_proj_w, in_proj_b, q, MQ, DD, DD);
    gemm_tf32<0><<<dim3((2*DD)/128, MKV/128), 256>>>(kvin, in_proj_w + (size_t)DD*DD,
                                                     in_proj_b + DD, kv, MKV, 2*DD, DD);

    // 3. attention
    attn_kernel<<<dim3(TT/64, HH, BB), 256>>>(q, kv, mask, ctx);

    // 4. output projection
    gemm_tf32<0><<<dim3(DD/128, MQ/128), 256>>>(ctx, out_proj_w, out_proj_b, attn, MQ, DD, DD);

    // 5. gate MLP
    pack_w1<<<(DD*KPAD + 255)/256, 256>>>(gate_w1, w1p);
    pack_gatein<<<(MQ*KPAD + 255)/256, 256>>>(target, attn, feat, gatein);
    gemm_tf32<1><<<dim3(DD/128, MQ/128), 256>>>(gatein, w1p, gate_b1, hbuf, MQ, DD, KPAD);
    gate2_kernel<<<MQ, 256>>>(hbuf, gate_w2, gate_b2, gate);

    // 6. fuse + residual + output LN (+ gate second output)
    float* gout = nullptr;
    if (out_size >= MQ*DD + MQ) gout = (float*)d_out + (size_t)MQ*DD;
    final_kernel<<<MQ, 256>>>(target, attn, gate, out_ln_w, out_ln_b, (float*)d_out, gout);
}

// round 4
// speedup vs baseline: 4.8620x; 4.0129x over previous
#include <cuda_runtime.h>
#include <math.h>
#include <stdint.h>

// Problem constants
#define BB 2
#define TT 1024
#define DD 1024
#define HH 16
#define DHH 64
#define KVL 2048              // S*L
#define MQ (BB*TT)            // 2048 query rows
#define MKV (BB*KVL)          // 4096 kv rows
#define KPAD 2080             // 2*D+3 padded to multiple of 32
#define KCAT (2*DD+3)         // 2051

// ---------------- scratch (static device memory; no allocations) -------------
__device__ float g_qin[MQ*DD];
__device__ float g_kvin[MKV*DD];
__device__ float g_q[MQ*DD];
__device__ float g_kv[MKV*2*DD];     // [:,0:1024]=k, [:,1024:2048]=v
__device__ float g_ctx[MQ*DD];
__device__ float g_attn[MQ*DD];
__device__ float g_gatein[MQ*KPAD];
__device__ float g_w1pad[DD*KPAD];
__device__ float g_h[MQ*DD];
__device__ float g_gate[MQ];

__device__ __forceinline__ float neg_inf() { return __int_as_float(0xff800000); }

__device__ __forceinline__ float gelu_exact(float x) {
    return 0.5f * x * (1.0f + erff(x * 0.70710678118654752f));
}

__device__ __forceinline__ uint32_t tf32r(float x) {
    uint32_t o;
    asm("cvt.rna.tf32.f32 %0, %1;" : "=r"(o) : "f"(x));
    return o;
}

__device__ __forceinline__ void mma_tf32(float* c, const uint32_t* a, const uint32_t* b) {
    asm volatile(
        "mma.sync.aligned.m16n8k8.row.col.f32.tf32.tf32.f32 "
        "{%0,%1,%2,%3}, {%4,%5,%6,%7}, {%8,%9}, {%0,%1,%2,%3};"
        : "+f"(c[0]), "+f"(c[1]), "+f"(c[2]), "+f"(c[3])
        : "r"(a[0]), "r"(a[1]), "r"(a[2]), "r"(a[3]), "r"(b[0]), "r"(b[1]));
}

// ---------------- LayerNorm over rows of length 1024 -------------------------
__global__ void __launch_bounds__(256) ln_kernel(const float* __restrict__ x,
                                                 const float* __restrict__ w,
                                                 const float* __restrict__ b,
                                                 float* __restrict__ out) {
    int row = blockIdx.x;
    int tid = threadIdx.x;
    const float4* xr = (const float4*)(x + (size_t)row * DD);
    float4 v = xr[tid];
    float s  = v.x + v.y + v.z + v.w;
    float sq = v.x*v.x + v.y*v.y + v.z*v.z + v.w*v.w;
    #pragma unroll
    for (int o = 16; o > 0; o >>= 1) {
        s  += __shfl_xor_sync(0xffffffffu, s, o);
        sq += __shfl_xor_sync(0xffffffffu, sq, o);
    }
    __shared__ float rs[8], rq[8];
    int wid = tid >> 5, lid = tid & 31;
    if (lid == 0) { rs[wid] = s; rq[wid] = sq; }
    __syncthreads();
    s = 0.f; sq = 0.f;
    #pragma unroll
    for (int i = 0; i < 8; i++) { s += rs[i]; sq += rq[i]; }
    float mean = s * (1.0f / DD);
    float var  = sq * (1.0f / DD) - mean * mean;
    float rstd = rsqrtf(var + 1e-5f);
    float4 wv = ((const float4*)w)[tid];
    float4 bv = ((const float4*)b)[tid];
    float4 o4;
    o4.x = (v.x - mean) * rstd * wv.x + bv.x;
    o4.y = (v.y - mean) * rstd * wv.y + bv.y;
    o4.z = (v.z - mean) * rstd * wv.z + bv.z;
    o4.w = (v.w - mean) * rstd * wv.w + bv.w;
    ((float4*)(out + (size_t)row * DD))[tid] = o4;
}

// ---------------- tf32 tensor-core GEMM: C[M,N] = A[M,K] * W[N,K]^T + bias ---
// Block 128x128x32, 256 threads = 8 warps (4x2), warp tile 32x64.
// smem holds pre-converted tf32 (uint32) -> no cvt in the inner loop.
template<int EPI>
__global__ void __launch_bounds__(256, 2) gemm_tf32(const float* __restrict__ A,
                                                    const float* __restrict__ W,
                                                    const float* __restrict__ bias,
                                                    float* __restrict__ C,
                                                    int M, int N, int K) {
    __shared__ uint32_t As[32][132];   // [k][m], padded, tf32 bits
    __shared__ uint32_t Ws[32][132];   // [k][n], padded, tf32 bits

    int tid  = threadIdx.x;
    int lane = tid & 31;
    int warp = tid >> 5;
    int wm = (warp & 3) * 32;
    int wn = (warp >> 2) * 64;
    int bm = blockIdx.y * 128, bn = blockIdx.x * 128;

    int lrow = tid >> 3;
    int lcol = (tid & 7) * 4;

    int qr = lane >> 2;
    int qc = lane & 3;

    float acc[2][8][4];
    #pragma unroll
    for (int i = 0; i < 2; i++)
        #pragma unroll
        for (int j = 0; j < 8; j++)
            #pragma unroll
            for (int t = 0; t < 4; t++) acc[i][j][t] = 0.f;

    for (int k0 = 0; k0 < K; k0 += 32) {
        #pragma unroll
        for (int u = 0; u < 4; u++) {
            int r = u * 32 + lrow;
            float4 av = *(const float4*)(A + (size_t)(bm + r) * K + k0 + lcol);
            float4 wv = *(const float4*)(W + (size_t)(bn + r) * K + k0 + lcol);
            As[lcol+0][r] = tf32r(av.x); As[lcol+1][r] = tf32r(av.y);
            As[lcol+2][r] = tf32r(av.z); As[lcol+3][r] = tf32r(av.w);
            Ws[lcol+0][r] = tf32r(wv.x); Ws[lcol+1][r] = tf32r(wv.y);
            Ws[lcol+2][r] = tf32r(wv.z); Ws[lcol+3][r] = tf32r(wv.w);
        }
        __syncthreads();

        #pragma unroll
        for (int kk = 0; kk < 4; kk++) {
            int kb = kk * 8;
            uint32_t af[2][4];
            #pragma unroll
            for (int mt = 0; mt < 2; mt++) {
                int mb = wm + mt * 16;
                af[mt][0] = As[kb + qc    ][mb + qr    ];
                af[mt][1] = As[kb + qc    ][mb + qr + 8];
                af[mt][2] = As[kb + qc + 4][mb + qr    ];
                af[mt][3] = As[kb + qc + 4][mb + qr + 8];
            }
            uint32_t bf[8][2];
            #pragma unroll
            for (int nt = 0; nt < 8; nt++) {
                int nb = wn + nt * 8;
                bf[nt][0] = Ws[kb + qc    ][nb + qr];
                bf[nt][1] = Ws[kb + qc + 4][nb + qr];
            }
            #pragma unroll
            for (int mt = 0; mt < 2; mt++)
                #pragma unroll
                for (int nt = 0; nt < 8; nt++)
                    mma_tf32(acc[mt][nt], af[mt], bf[nt]);
        }
        __syncthreads();
    }

    #pragma unroll
    for (int mt = 0; mt < 2; mt++) {
        int row0 = bm + wm + mt * 16 + qr;
        #pragma unroll
        for (int nt = 0; nt < 8; nt++) {
            int col = bn + wn + nt * 8 + qc * 2;
            float2 bi = *(const float2*)(bias + col);
            float v0 = acc[mt][nt][0] + bi.x;
            float v1 = acc[mt][nt][1] + bi.y;
            float v2 = acc[mt][nt][2] + bi.x;
            float v3 = acc[mt][nt][3] + bi.y;
            if (EPI == 1) {
                v0 = gelu_exact(v0); v1 = gelu_exact(v1);
                v2 = gelu_exact(v2); v3 = gelu_exact(v3);
            }
            *(float2*)(C + (size_t)row0 * N + col)       = make_float2(v0, v1);
            *(float2*)(C + (size_t)(row0 + 8) * N + col) = make_float2(v2, v3);
        }
    }
}

// ---------------- tensor-core flash attention (tf32 mma, fp32 softmax) -------
// grid (T/64, H, B), 128 threads (4 warps). Warp w owns q rows m0=16w..16w+15.
// KPs: K tile [kv][d] stride 68 (tf32), reused as P [q][kv] stride 68.
// Vs:  V tile [kv][d] stride 72 (tf32). mask nonzero = valid.
__global__ void __launch_bounds__(128) attn_tc(const float* __restrict__ Q,
                                               const float* __restrict__ KVb,
                                               const int* __restrict__ mask,
                                               float* __restrict__ O) {
    __shared__ uint32_t KPs[64*68];
    __shared__ uint32_t Vs[64*72];
    __shared__ int ms[64];

    int tid  = threadIdx.x;
    int lane = tid & 31;
    int warp = tid >> 5;
    int qr = lane >> 2, qc = lane & 3;
    int m0 = warp * 16;
    int b = blockIdx.z, h = blockIdx.y;
    int t0 = blockIdx.x * 64;

    // stage Q tile (scaled by 1/8) into KPs as tf32
    #pragma unroll
    for (int u = 0; u < 8; u++) {
        int f = u * 128 + tid;
        int row = f >> 4, c4 = f & 15;
        float4 t = *(const float4*)(Q + ((size_t)(b*TT + t0 + row))*DD + h*DHH + c4*4);
        *(uint4*)&KPs[row*68 + c4*4] = make_uint4(tf32r(t.x*0.125f), tf32r(t.y*0.125f),
                                                  tf32r(t.z*0.125f), tf32r(t.w*0.125f));
    }
    __syncthreads();

    // persistent Q A-fragments: qf[k8][4]
    uint32_t qf[8][4];
    #pragma unroll
    for (int k8 = 0; k8 < 8; k8++) {
        qf[k8][0] = KPs[(m0+qr  )*68 + k8*8 + qc    ];
        qf[k8][1] = KPs[(m0+qr+8)*68 + k8*8 + qc    ];
        qf[k8][2] = KPs[(m0+qr  )*68 + k8*8 + qc + 4];
        qf[k8][3] = KPs[(m0+qr+8)*68 + k8*8 + qc + 4];
    }

    float o[8][4];
    #pragma unroll
    for (int nt = 0; nt < 8; nt++)
        #pragma unroll
        for (int t = 0; t < 4; t++) o[nt][t] = 0.f;
    float mrow0 = neg_inf(), mrow1 = neg_inf();
    float l0 = 0.f, l1 = 0.f;

    for (int it = 0; it < KVL/64; it++) {
        int kv0 = it * 64;
        __syncthreads();   // prior PV reads of KPs/Vs complete
        #pragma unroll
        for (int u = 0; u < 8; u++) {
            int f = u * 128 + tid;
            int row = f >> 4, c4 = f & 15;
            const float* base = KVb + ((size_t)(b*KVL + kv0 + row))*(2*DD) + h*DHH;
            float4 k4 = *(const float4*)(base + c4*4);
            float4 v4 = *(const float4*)(base + DD + c4*4);
            *(uint4*)&KPs[row*68 + c4*4] = make_uint4(tf32r(k4.x), tf32r(k4.y),
                                                      tf32r(k4.z), tf32r(k4.w));
            *(uint4*)&Vs[row*72 + c4*4]  = make_uint4(tf32r(v4.x), tf32r(v4.y),
                                                      tf32r(v4.z), tf32r(v4.w));
        }
        if (tid < 64) ms[tid] = mask[(size_t)b*KVL + kv0 + tid];
        __syncthreads();

        // S = Q @ K^T  (per-warp 16x64)
        float s[8][4];
        #pragma unroll
        for (int nt = 0; nt < 8; nt++)
            #pragma unroll
            for (int t = 0; t < 4; t++) s[nt][t] = 0.f;
        #pragma unroll
        for (int k8 = 0; k8 < 8; k8++) {
            #pragma unroll
            for (int nt = 0; nt < 8; nt++) {
                uint32_t bf[2];
                bf[0] = KPs[(nt*8+qr)*68 + k8*8 + qc    ];
                bf[1] = KPs[(nt*8+qr)*68 + k8*8 + qc + 4];
                mma_tf32(s[nt], qf[k8], bf);
            }
        }

        // mask + online softmax (rows m0+qr and m0+qr+8)
        float tmax0 = neg_inf(), tmax1 = neg_inf();
        #pragma unroll
        for (int nt = 0; nt < 8; nt++) {
            int c0 = nt*8 + 2*qc;
            if (ms[c0] == 0)     { s[nt][0] = neg_inf(); s[nt][2] = neg_inf(); }
            if (ms[c0 + 1] == 0) { s[nt][1] = neg_inf(); s[nt][3] = neg_inf(); }
            tmax0 = fmaxf(tmax0, fmaxf(s[nt][0], s[nt][1]));
            tmax1 = fmaxf(tmax1, fmaxf(s[nt][2], s[nt][3]));
        }
        tmax0 = fmaxf(tmax0, __shfl_xor_sync(0xffffffffu, tmax0, 1));
        tmax0 = fmaxf(tmax0, __shfl_xor_sync(0xffffffffu, tmax0, 2));
        tmax1 = fmaxf(tmax1, __shfl_xor_sync(0xffffffffu, tmax1, 1));
        tmax1 = fmaxf(tmax1, __shfl_xor_sync(0xffffffffu, tmax1, 2));
        float mn0 = fmaxf(mrow0, tmax0), mb0 = fmaxf(mn0, -1e30f);
        float mn1 = fmaxf(mrow1, tmax1), mb1 = fmaxf(mn1, -1e30f);
        float corr0 = __expf(mrow0 - mb0);
        float corr1 = __expf(mrow1 - mb1);
        float ts0 = 0.f, ts1 = 0.f;
        #pragma unroll
        for (int nt = 0; nt < 8; nt++) {
            s[nt][0] = __expf(s[nt][0] - mb0);
            s[nt][1] = __expf(s[nt][1] - mb0);
            s[nt][2] = __expf(s[nt][2] - mb1);
            s[nt][3] = __expf(s[nt][3] - mb1);
            ts0 += s[nt][0] + s[nt][1];
            ts1 += s[nt][2] + s[nt][3];
        }
        ts0 += __shfl_xor_sync(0xffffffffu, ts0, 1);
        ts0 += __shfl_xor_sync(0xffffffffu, ts0, 2);
        ts1 += __shfl_xor_sync(0xffffffffu, ts1, 1);
        ts1 += __shfl_xor_sync(0xffffffffu, ts1, 2);
        l0 = l0 * corr0 + ts0;  mrow0 = mn0;
        l1 = l1 * corr1 + ts1;  mrow1 = mn1;
        #pragma unroll
        for (int nt = 0; nt < 8; nt++) {
            o[nt][0] *= corr0; o[nt][1] *= corr0;
            o[nt][2] *= corr1; o[nt][3] *= corr1;
        }

        __syncthreads();   // all warps done reading K tile
        // write P (tf32) into KPs: [q][kv] stride 68
        #pragma unroll
        for (int nt = 0; nt < 8; nt++) {
            int c0 = nt*8 + 2*qc;
            *(uint2*)&KPs[(m0+qr  )*68 + c0] = make_uint2(tf32r(s[nt][0]), tf32r(s[nt][1]));
            *(uint2*)&KPs[(m0+qr+8)*68 + c0] = make_uint2(tf32r(s[nt][2]), tf32r(s[nt][3]));
        }
        __syncthreads();

        // O += P @ V
        #pragma unroll
        for (int k8 = 0; k8 < 8; k8++) {
            uint32_t af[4];
            af[0] = KPs[(m0+qr  )*68 + k8*8 + qc    ];
            af[1] = KPs[(m0+qr+8)*68 + k8*8 + qc    ];
            af[2] = KPs[(m0+qr  )*68 + k8*8 + qc + 4];
            af[3] = KPs[(m0+qr+8)*68 + k8*8 + qc + 4];
            #pragma unroll
            for (int nt = 0; nt < 8; nt++) {
                uint32_t bf[2];
                bf[0] = Vs[(k8*8+qc  )*72 + nt*8 + qr];
                bf[1] = Vs[(k8*8+qc+4)*72 + nt*8 + qr];
                mma_tf32(o[nt], af, bf);
            }
        }
    }

    float i0 = 1.f / l0, i1 = 1.f / l1;
    float* orow0 = O + ((size_t)(b*TT + t0 + m0 + qr))*DD + h*DHH;
    float* orow1 = orow0 + (size_t)8*DD;
    #pragma unroll
    for (int nt = 0; nt < 8; nt++) {
        int c0 = nt*8 + 2*qc;
        *(float2*)(orow0 + c0) = make_float2(o[nt][0]*i0, o[nt][1]*i0);
        *(float2*)(orow1 + c0) = make_float2(o[nt][2]*i1, o[nt][3]*i1);
    }
}

// ---------------- pack kernels -----------------------------------------------
__global__ void pack_gatein(const float* __restrict__ target,
                            const float* __restrict__ attn,
                            const float* __restrict__ feat,
                            float* __restrict__ out) {
    int idx = blockIdx.x * blockDim.x + threadIdx.x;
    if (idx >= MQ * KPAD) return;
    int m = idx / KPAD, j = idx % KPAD;
    float v;
    if (j < DD)            v = target[(size_t)m*DD + j];
    else if (j < 2*DD)     v = attn[(size_t)m*DD + (j - DD)];
    else if (j < KCAT)     v = feat[(size_t)m*3 + (j - 2*DD)];
    else                   v = 0.f;
    out[idx] = v;
}

__global__ void pack_w1(const float* __restrict__ w1, float* __restrict__ out) {
    int idx = blockIdx.x * blockDim.x + threadIdx.x;
    if (idx >= DD * KPAD) return;
    int n = idx / KPAD, j = idx % KPAD;
    out[idx] = (j < KCAT) ? w1[(size_t)n*KCAT + j] : 0.f;
}

// ---------------- gate = sigmoid(h . w2 + b2) ---------------------------------
__global__ void __launch_bounds__(256) gate2_kernel(const float* __restrict__ hbuf,
                                                    const float* __restrict__ w2,
                                                    const float* __restrict__ b2,
                                                    float* __restrict__ gate) {
    int row = blockIdx.x;
    int tid = threadIdx.x;
    float4 hv = ((const float4*)(hbuf + (size_t)row * DD))[tid];
    float4 wv = ((const float4*)w2)[tid];
    float s = hv.x*wv.x + hv.y*wv.y + hv.z*wv.z + hv.w*wv.w;
    #pragma unroll
    for (int o = 16; o > 0; o >>= 1) s += __shfl_xor_sync(0xffffffffu, s, o);
    __shared__ float rs[8];
    int wid = tid >> 5, lid = tid & 31;
    if (lid == 0) rs[wid] = s;
    __syncthreads();
    if (tid == 0) {
        float tot = 0.f;
        #pragma unroll
        for (int i = 0; i < 8; i++) tot += rs[i];
        gate[row] = 1.f / (1.f + __expf(-(tot + b2[0])));
    }
}

// ---------------- fuse + residual + output LN --------------------------------
__global__ void __launch_bounds__(256) final_kernel(const float* __restrict__ target,
                                                    const float* __restrict__ attn,
                                                    const float* __restrict__ gate,
                                                    const float* __restrict__ w,
                                                    const float* __restrict__ bparm,
                                                    float* __restrict__ out,
                                                    float* __restrict__ gate_out) {
    int row = blockIdx.x;
    int tid = threadIdx.x;
    float g = gate[row];
    float4 t4 = ((const float4*)(target + (size_t)row * DD))[tid];
    float4 a4 = ((const float4*)(attn   + (size_t)row * DD))[tid];
    float4 x;
    x.x = (2.f - g)*t4.x + g*a4.x;
    x.y = (2.f - g)*t4.y + g*a4.y;
    x.z = (2.f - g)*t4.z + g*a4.z;
    x.w = (2.f - g)*t4.w + g*a4.w;
    float s  = x.x + x.y + x.z + x.w;
    float sq = x.x*x.x + x.y*x.y + x.z*x.z + x.w*x.w;
    #pragma unroll
    for (int o = 16; o > 0; o >>= 1) {
        s  += __shfl_xor_sync(0xffffffffu, s, o);
        sq += __shfl_xor_sync(0xffffffffu, sq, o);
    }
    __shared__ float rs[8], rq[8];
    int wid = tid >> 5, lid = tid & 31;
    if (lid == 0) { rs[wid] = s; rq[wid] = sq; }
    __syncthreads();
    s = 0.f; sq = 0.f;
    #pragma unroll
    for (int i = 0; i < 8; i++) { s += rs[i]; sq += rq[i]; }
    float mean = s * (1.0f / DD);
    float var  = sq * (1.0f / DD) - mean * mean;
    float rstd = rsqrtf(var + 1e-5f);
    float4 wv = ((const float4*)w)[tid];
    float4 bv = ((const float4*)bparm)[tid];
    float4 o4;
    o4.x = (x.x - mean)*rstd*wv.x + bv.x;
    o4.y = (x.y - mean)*rstd*wv.y + bv.y;
    o4.z = (x.z - mean)*rstd*wv.z + bv.z;
    o4.w = (x.w - mean)*rstd*wv.w + bv.w;
    ((float4*)(out + (size_t)row * DD))[tid] = o4;
    if (gate_out && tid == 0) gate_out[row] = g;
}

// ---------------- launch ------------------------------------------------------
extern "C" void kernel_launch(void* const* d_in, const int* in_sizes, int n_in,
                              void* d_out, int out_size) {
    const float* target   = (const float*)d_in[0];
    const float* support  = (const float*)d_in[1];
    const float* feat     = (const float*)d_in[2];
    const int*   mask     = (const int*)d_in[3];
    const float* ln_q_w   = (const float*)d_in[4];
    const float* ln_q_b   = (const float*)d_in[5];
    const float* ln_kv_w  = (const float*)d_in[6];
    const float* ln_kv_b  = (const float*)d_in[7];
    const float* out_ln_w = (const float*)d_in[8];
    const float* out_ln_b = (const float*)d_in[9];
    const float* in_proj_w  = (const float*)d_in[10];
    const float* in_proj_b  = (const float*)d_in[11];
    const float* out_proj_w = (const float*)d_in[12];
    const float* out_proj_b = (const float*)d_in[13];
    const float* gate_w1 = (const float*)d_in[14];
    const float* gate_b1 = (const float*)d_in[15];
    const float* gate_w2 = (const float*)d_in[16];
    const float* gate_b2 = (const float*)d_in[17];

    float *qin, *kvin, *q, *kv, *ctx, *attn, *gatein, *w1p, *hbuf, *gate;
    cudaGetSymbolAddress((void**)&qin,    g_qin);
    cudaGetSymbolAddress((void**)&kvin,   g_kvin);
    cudaGetSymbolAddress((void**)&q,      g_q);
    cudaGetSymbolAddress((void**)&kv,     g_kv);
    cudaGetSymbolAddress((void**)&ctx,    g_ctx);
    cudaGetSymbolAddress((void**)&attn,   g_attn);
    cudaGetSymbolAddress((void**)&gatein, g_gatein);
    cudaGetSymbolAddress((void**)&w1p,    g_w1pad);
    cudaGetSymbolAddress((void**)&hbuf,   g_h);
    cudaGetSymbolAddress((void**)&gate,   g_gate);

    // 1. input layernorms
    ln_kernel<<<MQ, 256>>>(target, ln_q_w, ln_q_b, qin);
    ln_kernel<<<MKV, 256>>>(support, ln_kv_w, ln_kv_b, kvin);

    // 2. projections (q, fused kv) — tf32 tensor cores
    gemm_tf32<0><<<dim3(DD/128, MQ/128), 256>>>(qin, in_proj_w, in_proj_b, q, MQ, DD, DD);
    gemm_tf32<0><<<dim3((2*DD)/128, MKV/128), 256>>>(kvin, in_proj_w + (size_t)DD*DD,
                                                     in_proj_b + DD, kv, MKV, 2*DD, DD);

    // 3. attention — tf32 tensor cores
    attn_tc<<<dim3(TT/64, HH, BB), 128>>>(q, kv, mask, ctx);

    // 4. output projection
    gemm_tf32<0><<<dim3(DD/128, MQ/128), 256>>>(ctx, out_proj_w, out_proj_b, attn, MQ, DD, DD);

    // 5. gate MLP
    pack_w1<<<(DD*KPAD + 255)/256, 256>>>(gate_w1, w1p);
    pack_gatein<<<(MQ*KPAD + 255)/256, 256>>>(target, attn, feat, gatein);
    gemm_tf32<1><<<dim3(DD/128, MQ/128), 256>>>(gatein, w1p, gate_b1, hbuf, MQ, DD, KPAD);
    gate2_kernel<<<MQ, 256>>>(hbuf, gate_w2, gate_b2, gate);

    // 6. fuse + residual + output LN (+ gate second output)
    float* gout = nullptr;
    if (out_size >= MQ*DD + MQ) gout = (float*)d_out + (size_t)MQ*DD;
    final_kernel<<<MQ, 256>>>(target, attn, gate, out_ln_w, out_ln_b, (float*)d_out, gout);
}

// round 5
// speedup vs baseline: 10.9493x; 2.2520x over previous
#include <cuda_runtime.h>
#include <cuda_bf16.h>
#include <math.h>
#include <stdint.h>

#define BB 2
#define TT 1024
#define DD 1024
#define HH 16
#define DHH 64
#define KVL 2048
#define MQ (BB*TT)
#define MKV (BB*KVL)
#define KPAD 2080
#define KCAT (2*DD+3)

typedef __nv_bfloat16 bf16;
typedef __nv_bfloat162 bf162;

// ---------------- scratch (static device memory; no allocations) -------------
__device__ bf16  g_qin[MQ*DD];
__device__ bf16  g_kvin[MKV*DD];
__device__ bf16  g_q[MQ*DD];
__device__ bf16  g_kv[MKV*2*DD];     // [:,0:1024]=k, [:,1024:2048]=v (bf16)
__device__ bf16  g_ctx[MQ*DD];
__device__ float g_attn[MQ*DD];
__device__ bf16  g_gatein[MQ*KPAD];
__device__ bf16  g_w1pad[DD*KPAD];
__device__ bf16  g_ipw[3*DD*DD];
__device__ bf16  g_opw[DD*DD];
__device__ float g_h[MQ*DD];
__device__ float g_gate[MQ];

__device__ __forceinline__ float neg_inf() { return __int_as_float(0xff800000); }

__device__ __forceinline__ float gelu_exact(float x) {
    return 0.5f * x * (1.0f + erff(x * 0.70710678118654752f));
}

__device__ __forceinline__ uint32_t packbf(float a, float b) {
    bf162 t = __floats2bfloat162_rn(a, b);
    return *(uint32_t*)&t;
}

__device__ __forceinline__ void mma_bf16(float* c, const uint32_t* a, const uint32_t* b) {
    asm volatile(
        "mma.sync.aligned.m16n8k16.row.col.f32.bf16.bf16.f32 "
        "{%0,%1,%2,%3}, {%4,%5,%6,%7}, {%8,%9}, {%0,%1,%2,%3};"
        : "+f"(c[0]), "+f"(c[1]), "+f"(c[2]), "+f"(c[3])
        : "r"(a[0]), "r"(a[1]), "r"(a[2]), "r"(a[3]), "r"(b[0]), "r"(b[1]));
}

__device__ __forceinline__ void cp16(void* smem_dst, const void* gsrc) {
    uint32_t d = (uint32_t)__cvta_generic_to_shared(smem_dst);
    asm volatile("cp.async.cg.shared.global [%0], [%1], 16;\n" :: "r"(d), "l"(gsrc));
}
__device__ __forceinline__ void cp_commit() { asm volatile("cp.async.commit_group;\n"); }
template<int N> __device__ __forceinline__ void cp_wait() {
    asm volatile("cp.async.wait_group %0;\n" :: "n"(N));
}

// ---------------- fp32 -> bf16 converters -------------------------------------
__global__ void f2bf(const float* __restrict__ in, bf16* __restrict__ out, int n4) {
    int i = blockIdx.x * blockDim.x + threadIdx.x;
    if (i >= n4) return;
    float4 v = ((const float4*)in)[i];
    ((uint2*)out)[i] = make_uint2(packbf(v.x, v.y), packbf(v.z, v.w));
}

__global__ void pack_w1_bf(const float* __restrict__ w1, bf16* __restrict__ out) {
    int idx = blockIdx.x * blockDim.x + threadIdx.x;
    if (idx >= DD * KPAD) return;
    int n = idx / KPAD, j = idx % KPAD;
    out[idx] = __float2bfloat16((j < KCAT) ? w1[(size_t)n*KCAT + j] : 0.f);
}

__global__ void pack_gatein_bf(const float* __restrict__ target,
                               const float* __restrict__ attn,
                               const float* __restrict__ feat,
                               bf16* __restrict__ out) {
    int idx = blockIdx.x * blockDim.x + threadIdx.x;
    if (idx >= MQ * KPAD) return;
    int m = idx / KPAD, j = idx % KPAD;
    float v;
    if (j < DD)        v = target[(size_t)m*DD + j];
    else if (j < 2*DD) v = attn[(size_t)m*DD + (j - DD)];
    else if (j < KCAT) v = feat[(size_t)m*3 + (j - 2*DD)];
    else               v = 0.f;
    out[idx] = __float2bfloat16(v);
}

// ---------------- LayerNorm (fp32 in, bf16 out) -------------------------------
__global__ void __launch_bounds__(256) ln_bf(const float* __restrict__ x,
                                             const float* __restrict__ w,
                                             const float* __restrict__ b,
                                             bf16* __restrict__ out) {
    int row = blockIdx.x;
    int tid = threadIdx.x;
    const float4* xr = (const float4*)(x + (size_t)row * DD);
    float4 v = xr[tid];
    float s  = v.x + v.y + v.z + v.w;
    float sq = v.x*v.x + v.y*v.y + v.z*v.z + v.w*v.w;
    #pragma unroll
    for (int o = 16; o > 0; o >>= 1) {
        s  += __shfl_xor_sync(0xffffffffu, s, o);
        sq += __shfl_xor_sync(0xffffffffu, sq, o);
    }
    __shared__ float rs[8], rq[8];
    int wid = tid >> 5, lid = tid & 31;
    if (lid == 0) { rs[wid] = s; rq[wid] = sq; }
    __syncthreads();
    s = 0.f; sq = 0.f;
    #pragma unroll
    for (int i = 0; i < 8; i++) { s += rs[i]; sq += rq[i]; }
    float mean = s * (1.0f / DD);
    float var  = sq * (1.0f / DD) - mean * mean;
    float rstd = rsqrtf(var + 1e-5f);
    float4 wv = ((const float4*)w)[tid];
    float4 bv = ((const float4*)b)[tid];
    float o0 = (v.x - mean)*rstd*wv.x + bv.x;
    float o1 = (v.y - mean)*rstd*wv.y + bv.y;
    float o2 = (v.z - mean)*rstd*wv.z + bv.z;
    float o3 = (v.w - mean)*rstd*wv.w + bv.w;
    ((uint2*)(out + (size_t)row * DD))[tid] = make_uint2(packbf(o0, o1), packbf(o2, o3));
}

// ---------------- bf16 tensor-core GEMM: C = A[M,K] * W[N,K]^T + bias ---------
// Block 128x128x32, 256 threads, 8 warps (4x2), warp tile 32x64.
// smem holds bf16 pairs (uint32); cp.async + double buffer.
// EPI: 1 = exact GELU. OUTBF: 1 = bf16 output, 0 = fp32.
template<int EPI, int OUTBF>
__global__ void __launch_bounds__(256, 2) gemm_bf16(const bf16* __restrict__ A,
                                                    const bf16* __restrict__ W,
                                                    const float* __restrict__ bias,
                                                    void* __restrict__ Cp,
                                                    int M, int N, int K) {
    __shared__ uint32_t As[2][128][20];
    __shared__ uint32_t Ws[2][128][20];

    int tid  = threadIdx.x;
    int lane = tid & 31;
    int warp = tid >> 5;
    int wm = (warp & 3) * 32;
    int wn = (warp >> 2) * 64;
    int bm = blockIdx.y * 128, bn = blockIdx.x * 128;
    int qr = lane >> 2, qc = lane & 3;
    int nk = K >> 5;

    float acc[2][8][4];
    #pragma unroll
    for (int i = 0; i < 2; i++)
        #pragma unroll
        for (int j = 0; j < 8; j++)
            #pragma unroll
            for (int t = 0; t < 4; t++) acc[i][j][t] = 0.f;

    // prologue: stage 0
    {
        #pragma unroll
        for (int u = 0; u < 2; u++) {
            int chunk = u * 256 + tid;
            int row = chunk >> 2, c = (chunk & 3) * 4;
            cp16(&As[0][row][c], A + (size_t)(bm + row) * K + c * 2);
            cp16(&Ws[0][row][c], W + (size_t)(bn + row) * K + c * 2);
        }
        cp_commit();
    }

    for (int it = 0; it < nk; ++it) {
        int st = it & 1;
        if (it + 1 < nk) {
            int k0 = (it + 1) * 32;
            #pragma unroll
            for (int u = 0; u < 2; u++) {
                int chunk = u * 256 + tid;
                int row = chunk >> 2, c = (chunk & 3) * 4;
                cp16(&As[st^1][row][c], A + (size_t)(bm + row) * K + k0 + c * 2);
                cp16(&Ws[st^1][row][c], W + (size_t)(bn + row) * K + k0 + c * 2);
            }
            cp_commit();
            cp_wait<1>();
        } else {
            cp_wait<0>();
        }
        __syncthreads();

        #pragma unroll
        for (int s = 0; s < 2; s++) {
            int kp = s * 8;
            uint32_t af[2][4];
            #pragma unroll
            for (int mt = 0; mt < 2; mt++) {
                int mb = wm + mt * 16;
                af[mt][0] = As[st][mb + qr    ][kp + qc    ];
                af[mt][1] = As[st][mb + qr + 8][kp + qc    ];
                af[mt][2] = As[st][mb + qr    ][kp + qc + 4];
                af[mt][3] = As[st][mb + qr + 8][kp + qc + 4];
            }
            uint32_t bfr[8][2];
            #pragma unroll
            for (int nt = 0; nt < 8; nt++) {
                int nb = wn + nt * 8;
                bfr[nt][0] = Ws[st][nb + qr][kp + qc    ];
                bfr[nt][1] = Ws[st][nb + qr][kp + qc + 4];
            }
            #pragma unroll
            for (int mt = 0; mt < 2; mt++)
                #pragma unroll
                for (int nt = 0; nt < 8; nt++)
                    mma_bf16(acc[mt][nt], af[mt], bfr[nt]);
        }
        __syncthreads();
    }

    #pragma unroll
    for (int mt = 0; mt < 2; mt++) {
        int row0 = bm + wm + mt * 16 + qr;
        #pragma unroll
        for (int nt = 0; nt < 8; nt++) {
            int col = bn + wn + nt * 8 + qc * 2;
            float2 bi = *(const float2*)(bias + col);
            float v0 = acc[mt][nt][0] + bi.x;
            float v1 = acc[mt][nt][1] + bi.y;
            float v2 = acc[mt][nt][2] + bi.x;
            float v3 = acc[mt][nt][3] + bi.y;
            if (EPI == 1) {
                v0 = gelu_exact(v0); v1 = gelu_exact(v1);
                v2 = gelu_exact(v2); v3 = gelu_exact(v3);
            }
            if (OUTBF) {
                bf16* C = (bf16*)Cp;
                *(uint32_t*)(C + (size_t)row0 * N + col)       = packbf(v0, v1);
                *(uint32_t*)(C + (size_t)(row0 + 8) * N + col) = packbf(v2, v3);
            } else {
                float* C = (float*)Cp;
                *(float2*)(C + (size_t)row0 * N + col)       = make_float2(v0, v1);
                *(float2*)(C + (size_t)(row0 + 8) * N + col) = make_float2(v2, v3);
            }
        }
    }
}

// ---------------- bf16 tensor-core flash attention -----------------------------
// grid (T/64, H, B), 128 threads (4 warps). Warp w owns q rows 16w..16w+15.
// Ks: [kv][d] pairs, stride 36 words; reused for Q staging and P.
// Vs: [kv][d] pairs; PV B-fragments via ldmatrix.x2.trans.
__global__ void __launch_bounds__(128) attn_bf(const bf16* __restrict__ Q,
                                               const bf16* __restrict__ KVb,
                                               const int* __restrict__ mask,
                                               bf16* __restrict__ O) {
    __shared__ uint32_t Ks[64][36];
    __shared__ uint32_t Vs[64][36];
    __shared__ int ms[64];

    int tid  = threadIdx.x;
    int lane = tid & 31;
    int warp = tid >> 5;
    int qr = lane >> 2, qc = lane & 3;
    int m0 = warp * 16;
    int b = blockIdx.z, h = blockIdx.y;
    int t0 = blockIdx.x * 64;

    // stage Q tile (scaled by 1/8, exact in bf16) into Ks
    {
        bf162 sc = __floats2bfloat162_rn(0.125f, 0.125f);
        #pragma unroll
        for (int u = 0; u < 4; u++) {
            int chunk = u * 128 + tid;
            int row = chunk >> 3, c = chunk & 7;
            uint4 t = *(const uint4*)(Q + ((size_t)(b*TT + t0 + row))*DD + h*DHH + c*8);
            bf162* p = (bf162*)&t;
            p[0] = __hmul2(p[0], sc); p[1] = __hmul2(p[1], sc);
            p[2] = __hmul2(p[2], sc); p[3] = __hmul2(p[3], sc);
            *(uint4*)&Ks[row][c*4] = t;
        }
    }
    __syncthreads();

    uint32_t qf[4][4];
    #pragma unroll
    for (int s4 = 0; s4 < 4; s4++) {
        qf[s4][0] = Ks[m0+qr  ][s4*8 + qc    ];
        qf[s4][1] = Ks[m0+qr+8][s4*8 + qc    ];
        qf[s4][2] = Ks[m0+qr  ][s4*8 + qc + 4];
        qf[s4][3] = Ks[m0+qr+8][s4*8 + qc + 4];
    }

    float o[8][4];
    #pragma unroll
    for (int nt = 0; nt < 8; nt++)
        #pragma unroll
        for (int t = 0; t < 4; t++) o[nt][t] = 0.f;
    float mrow0 = neg_inf(), mrow1 = neg_inf();
    float l0 = 0.f, l1 = 0.f;

    uint32_t vbase = (uint32_t)__cvta_generic_to_shared(&Vs[lane & 15][0]);

    for (int it = 0; it < KVL/64; it++) {
        int kv0 = it * 64;
        __syncthreads();
        #pragma unroll
        for (int u = 0; u < 4; u++) {
            int chunk = u * 128 + tid;
            int row = chunk >> 3, c = chunk & 7;
            const bf16* base = KVb + ((size_t)(b*KVL + kv0 + row))*(2*DD) + h*DHH;
            *(uint4*)&Ks[row][c*4] = *(const uint4*)(base + c*8);
            *(uint4*)&Vs[row][c*4] = *(const uint4*)(base + DD + c*8);
        }
        if (tid < 64) ms[tid] = mask[(size_t)b*KVL + kv0 + tid];
        __syncthreads();

        // S = Q @ K^T  (per-warp 16x64, k=64 over 4 k16 steps)
        float s[8][4];
        #pragma unroll
        for (int nt = 0; nt < 8; nt++)
            #pragma unroll
            for (int t = 0; t < 4; t++) s[nt][t] = 0.f;
        #pragma unroll
        for (int s4 = 0; s4 < 4; s4++) {
            #pragma unroll
            for (int nt = 0; nt < 8; nt++) {
                uint32_t bfr[2];
                bfr[0] = Ks[nt*8 + qr][s4*8 + qc    ];
                bfr[1] = Ks[nt*8 + qr][s4*8 + qc + 4];
                mma_bf16(s[nt], qf[s4], bfr);
            }
        }

        // mask + online softmax (rows m0+qr, m0+qr+8)
        float tmax0 = neg_inf(), tmax1 = neg_inf();
        #pragma unroll
        for (int nt = 0; nt < 8; nt++) {
            int c0 = nt*8 + 2*qc;
            if (ms[c0] == 0)     { s[nt][0] = neg_inf(); s[nt][2] = neg_inf(); }
            if (ms[c0 + 1] == 0) { s[nt][1] = neg_inf(); s[nt][3] = neg_inf(); }
            tmax0 = fmaxf(tmax0, fmaxf(s[nt][0], s[nt][1]));
            tmax1 = fmaxf(tmax1, fmaxf(s[nt][2], s[nt][3]));
        }
        tmax0 = fmaxf(tmax0, __shfl_xor_sync(0xffffffffu, tmax0, 1));
        tmax0 = fmaxf(tmax0, __shfl_xor_sync(0xffffffffu, tmax0, 2));
        tmax1 = fmaxf(tmax1, __shfl_xor_sync(0xffffffffu, tmax1, 1));
        tmax1 = fmaxf(tmax1, __shfl_xor_sync(0xffffffffu, tmax1, 2));
        float mn0 = fmaxf(mrow0, tmax0), mb0 = fmaxf(mn0, -1e30f);
        float mn1 = fmaxf(mrow1, tmax1), mb1 = fmaxf(mn1, -1e30f);
        float corr0 = __expf(mrow0 - mb0);
        float corr1 = __expf(mrow1 - mb1);
        float ts0 = 0.f, ts1 = 0.f;
        #pragma unroll
        for (int nt = 0; nt < 8; nt++) {
            s[nt][0] = __expf(s[nt][0] - mb0);
            s[nt][1] = __expf(s[nt][1] - mb0);
            s[nt][2] = __expf(s[nt][2] - mb1);
            s[nt][3] = __expf(s[nt][3] - mb1);
            ts0 += s[nt][0] + s[nt][1];
            ts1 += s[nt][2] + s[nt][3];
        }
        ts0 += __shfl_xor_sync(0xffffffffu, ts0, 1);
        ts0 += __shfl_xor_sync(0xffffffffu, ts0, 2);
        ts1 += __shfl_xor_sync(0xffffffffu, ts1, 1);
        ts1 += __shfl_xor_sync(0xffffffffu, ts1, 2);
        l0 = l0 * corr0 + ts0;  mrow0 = mn0;
        l1 = l1 * corr1 + ts1;  mrow1 = mn1;
        #pragma unroll
        for (int nt = 0; nt < 8; nt++) {
            o[nt][0] *= corr0; o[nt][1] *= corr0;
            o[nt][2] *= corr1; o[nt][3] *= corr1;
        }

        __syncthreads();   // all warps done reading K tile
        // write P (bf16 pairs) into Ks: [q][kv-pairs] stride 36
        #pragma unroll
        for (int nt = 0; nt < 8; nt++) {
            Ks[m0+qr  ][nt*4 + qc] = packbf(s[nt][0], s[nt][1]);
            Ks[m0+qr+8][nt*4 + qc] = packbf(s[nt][2], s[nt][3]);
        }
        __syncthreads();

        // O += P @ V  (V B-frags via ldmatrix.x2.trans)
        #pragma unroll
        for (int s4 = 0; s4 < 4; s4++) {
            uint32_t af[4];
            af[0] = Ks[m0+qr  ][s4*8 + qc    ];
            af[1] = Ks[m0+qr+8][s4*8 + qc    ];
            af[2] = Ks[m0+qr  ][s4*8 + qc + 4];
            af[3] = Ks[m0+qr+8][s4*8 + qc + 4];
            #pragma unroll
            for (int nt = 0; nt < 8; nt++) {
                uint32_t b0, b1;
                uint32_t addr = vbase + (uint32_t)((s4*16*36 + nt*4) * 4);
                asm volatile("ldmatrix.sync.aligned.m8n8.x2.trans.shared.b16 {%0,%1}, [%2];"
                             : "=r"(b0), "=r"(b1) : "r"(addr));
                uint32_t bfr[2] = {b0, b1};
                mma_bf16(o[nt], af, bfr);
            }
        }
    }

    float i0 = 1.f / l0, i1 = 1.f / l1;
    bf16* or0 = O + ((size_t)(b*TT + t0 + m0 + qr))*DD + h*DHH;
    bf16* or1 = or0 + (size_t)8*DD;
    #pragma unroll
    for (int nt = 0; nt < 8; nt++) {
        int c0 = nt*8 + 2*qc;
        *(uint32_t*)(or0 + c0) = packbf(o[nt][0]*i0, o[nt][1]*i0);
        *(uint32_t*)(or1 + c0) = packbf(o[nt][2]*i1, o[nt][3]*i1);
    }
}

// ---------------- gate = sigmoid(h . w2 + b2) ---------------------------------
__global__ void __launch_bounds__(256) gate2_kernel(const float* __restrict__ hbuf,
                                                    const float* __restrict__ w2,
                                                    const float* __restrict__ b2,
                                                    float* __restrict__ gate) {
    int row = blockIdx.x;
    int tid = threadIdx.x;
    float4 hv = ((const float4*)(hbuf + (size_t)row * DD))[tid];
    float4 wv = ((const float4*)w2)[tid];
    float s = hv.x*wv.x + hv.y*wv.y + hv.z*wv.z + hv.w*wv.w;
    #pragma unroll
    for (int o = 16; o > 0; o >>= 1) s += __shfl_xor_sync(0xffffffffu, s, o);
    __shared__ float rs[8];
    int wid = tid >> 5, lid = tid & 31;
    if (lid == 0) rs[wid] = s;
    __syncthreads();
    if (tid == 0) {
        float tot = 0.f;
        #pragma unroll
        for (int i = 0; i < 8; i++) tot += rs[i];
        gate[row] = 1.f / (1.f + __expf(-(tot + b2[0])));
    }
}

// ---------------- fuse + residual + output LN ---------------------------------
__global__ void __launch_bounds__(256) final_kernel(const float* __restrict__ target,
                                                    const float* __restrict__ attn,
                                                    const float* __restrict__ gate,
                                                    const float* __restrict__ w,
                                                    const float* __restrict__ bparm,
                                                    float* __restrict__ out,
                                                    float* __restrict__ gate_out) {
    int row = blockIdx.x;
    int tid = threadIdx.x;
    float g = gate[row];
    float4 t4 = ((const float4*)(target + (size_t)row * DD))[tid];
    float4 a4 = ((const float4*)(attn   + (size_t)row * DD))[tid];
    float4 x;
    x.x = (2.f - g)*t4.x + g*a4.x;
    x.y = (2.f - g)*t4.y + g*a4.y;
    x.z = (2.f - g)*t4.z + g*a4.z;
    x.w = (2.f - g)*t4.w + g*a4.w;
    float s  = x.x + x.y + x.z + x.w;
    float sq = x.x*x.x + x.y*x.y + x.z*x.z + x.w*x.w;
    #pragma unroll
    for (int o = 16; o > 0; o >>= 1) {
        s  += __shfl_xor_sync(0xffffffffu, s, o);
        sq += __shfl_xor_sync(0xffffffffu, sq, o);
    }
    __shared__ float rs[8], rq[8];
    int wid = tid >> 5, lid = tid & 31;
    if (lid == 0) { rs[wid] = s; rq[wid] = sq; }
    __syncthreads();
    s = 0.f; sq = 0.f;
    #pragma unroll
    for (int i = 0; i < 8; i++) { s += rs[i]; sq += rq[i]; }
    float mean = s * (1.0f / DD);
    float var  = sq * (1.0f / DD) - mean * mean;
    float rstd = rsqrtf(var + 1e-5f);
    float4 wv = ((const float4*)w)[tid];
    float4 bv = ((const float4*)bparm)[tid];
    float4 o4;
    o4.x = (x.x - mean)*rstd*wv.x + bv.x;
    o4.y = (x.y - mean)*rstd*wv.y + bv.y;
    o4.z = (x.z - mean)*rstd*wv.z + bv.z;
    o4.w = (x.w - mean)*rstd*wv.w + bv.w;
    ((float4*)(out + (size_t)row * DD))[tid] = o4;
    if (gate_out && tid == 0) gate_out[row] = g;
}

// ---------------- launch --------------------------------------------------------
extern "C" void kernel_launch(void* const* d_in, const int* in_sizes, int n_in,
                              void* d_out, int out_size) {
    const float* target   = (const float*)d_in[0];
    const float* support  = (const float*)d_in[1];
    const float* feat     = (const float*)d_in[2];
    const int*   mask     = (const int*)d_in[3];
    const float* ln_q_w   = (const float*)d_in[4];
    const float* ln_q_b   = (const float*)d_in[5];
    const float* ln_kv_w  = (const float*)d_in[6];
    const float* ln_kv_b  = (const float*)d_in[7];
    const float* out_ln_w = (const float*)d_in[8];
    const float* out_ln_b = (const float*)d_in[9];
    const float* in_proj_w  = (const float*)d_in[10];
    const float* in_proj_b  = (const float*)d_in[11];
    const float* out_proj_w = (const float*)d_in[12];
    const float* out_proj_b = (const float*)d_in[13];
    const float* gate_w1 = (const float*)d_in[14];
    const float* gate_b1 = (const float*)d_in[15];
    const float* gate_w2 = (const float*)d_in[16];
    const float* gate_b2 = (const float*)d_in[17];

    bf16 *qin, *kvin, *q, *kv, *ctx, *gatein, *w1p, *ipw, *opw;
    float *attn, *hbuf, *gate;
    cudaGetSymbolAddress((void**)&qin,    g_qin);
    cudaGetSymbolAddress((void**)&kvin,   g_kvin);
    cudaGetSymbolAddress((void**)&q,      g_q);
    cudaGetSymbolAddress((void**)&kv,     g_kv);
    cudaGetSymbolAddress((void**)&ctx,    g_ctx);
    cudaGetSymbolAddress((void**)&attn,   g_attn);
    cudaGetSymbolAddress((void**)&gatein, g_gatein);
    cudaGetSymbolAddress((void**)&w1p,    g_w1pad);
    cudaGetSymbolAddress((void**)&ipw,    g_ipw);
    cudaGetSymbolAddress((void**)&opw,    g_opw);
    cudaGetSymbolAddress((void**)&hbuf,   g_h);
    cudaGetSymbolAddress((void**)&gate,   g_gate);

    // 0. weight conversions (bf16)
    f2bf<<<(3*DD*DD/4 + 255)/256, 256>>>(in_proj_w, ipw, 3*DD*DD/4);
    f2bf<<<(DD*DD/4 + 255)/256, 256>>>(out_proj_w, opw, DD*DD/4);
    pack_w1_bf<<<(DD*KPAD + 255)/256, 256>>>(gate_w1, w1p);

    // 1. input layernorms -> bf16
    ln_bf<<<MQ, 256>>>(target, ln_q_w, ln_q_b, qin);
    ln_bf<<<MKV, 256>>>(support, ln_kv_w, ln_kv_b, kvin);

    // 2. projections (q, fused kv) — bf16 tensor cores
    gemm_bf16<0,1><<<dim3(DD/128, MQ/128), 256>>>(qin, ipw, in_proj_b, q, MQ, DD, DD);
    gemm_bf16<0,1><<<dim3((2*DD)/128, MKV/128), 256>>>(kvin, ipw + (size_t)DD*DD,
                                                       in_proj_b + DD, kv, MKV, 2*DD, DD);

    // 3. attention — bf16 tensor cores
    attn_bf<<<dim3(TT/64, HH, BB), 128>>>(q, kv, mask, ctx);

    // 4. output projection (fp32 out for residual path)
    gemm_bf16<0,0><<<dim3(DD/128, MQ/128), 256>>>(ctx, opw, out_proj_b, attn, MQ, DD, DD);

    // 5. gate MLP
    pack_gatein_bf<<<(MQ*KPAD + 255)/256, 256>>>(target, attn, feat, gatein);
    gemm_bf16<1,0><<<dim3(DD/128, MQ/128), 256>>>(gatein, w1p, gate_b1, hbuf, MQ, DD, KPAD);
    gate2_kernel<<<MQ, 256>>>(hbuf, gate_w2, gate_b2, gate);

    // 6. fuse + residual + output LN (+ gate second output)
    float* gout = nullptr;
    if (out_size >= MQ*DD + MQ) gout = (float*)d_out + (size_t)MQ*DD;
    final_kernel<<<MQ, 256>>>(target, attn, gate, out_ln_w, out_ln_b, (float*)d_out, gout);
}

// round 7
// speedup vs baseline: 13.4211x; 1.2257x over previous
#include <cuda_runtime.h>
#include <cuda_bf16.h>
#include <math.h>
#include <stdint.h>

#define BB 2
#define TT 1024
#define DD 1024
#define HH 16
#define DHH 64
#define KVL 2048
#define MQ (BB*TT)
#define MKV (BB*KVL)
#define KPAD 2112            // 2*D+3 padded to multiple of 64
#define KCAT (2*DD+3)

typedef __nv_bfloat16 bf16;
typedef __nv_bfloat162 bf162;

// ---------------- scratch (static device memory; no allocations) -------------
__device__ bf16  g_qin[MQ*DD];
__device__ bf16  g_kvin[MKV*DD];
__device__ bf16  g_q[MQ*DD];
__device__ bf16  g_kv[MKV*2*DD];
__device__ bf16  g_ctx[MQ*DD];
__device__ float g_attn[MQ*DD];
__device__ bf16  g_gatein[MQ*KPAD];
__device__ bf16  g_w1pad[DD*KPAD];
__device__ bf16  g_ipw[3*DD*DD];
__device__ bf16  g_opw[DD*DD];
__device__ float g_h[MQ*DD];
__device__ float g_gate[MQ];

__device__ __forceinline__ float neg_inf() { return __int_as_float(0xff800000); }

__device__ __forceinline__ float gelu_exact(float x) {
    return 0.5f * x * (1.0f + erff(x * 0.70710678118654752f));
}

__device__ __forceinline__ uint32_t packbf(float a, float b) {
    bf162 t = __floats2bfloat162_rn(a, b);
    return *(uint32_t*)&t;
}

__device__ __forceinline__ void mma_bf16(float* c, const uint32_t* a, const uint32_t* b) {
    asm volatile(
        "mma.sync.aligned.m16n8k16.row.col.f32.bf16.bf16.f32 "
        "{%0,%1,%2,%3}, {%4,%5,%6,%7}, {%8,%9}, {%0,%1,%2,%3};"
        : "+f"(c[0]), "+f"(c[1]), "+f"(c[2]), "+f"(c[3])
        : "r"(a[0]), "r"(a[1]), "r"(a[2]), "r"(a[3]), "r"(b[0]), "r"(b[1]));
}

__device__ __forceinline__ void ldm_x4(uint32_t* r, uint32_t addr) {
    asm volatile("ldmatrix.sync.aligned.m8n8.x4.shared.b16 {%0,%1,%2,%3}, [%4];"
                 : "=r"(r[0]), "=r"(r[1]), "=r"(r[2]), "=r"(r[3]) : "r"(addr));
}

__device__ __forceinline__ void cp16(void* smem_dst, const void* gsrc) {
    uint32_t d = (uint32_t)__cvta_generic_to_shared(smem_dst);
    asm volatile("cp.async.cg.shared.global [%0], [%1], 16;\n" :: "r"(d), "l"(gsrc));
}
__device__ __forceinline__ void cp_commit() { asm volatile("cp.async.commit_group;\n"); }
template<int N> __device__ __forceinline__ void cp_wait() {
    asm volatile("cp.async.wait_group %0;\n" :: "n"(N));
}

// ---------------- fp32 -> bf16 converters -------------------------------------
__global__ void f2bf(const float* __restrict__ in, bf16* __restrict__ out, int n4) {
    int i = blockIdx.x * blockDim.x + threadIdx.x;
    if (i >= n4) return;
    float4 v = ((const float4*)in)[i];
    ((uint2*)out)[i] = make_uint2(packbf(v.x, v.y), packbf(v.z, v.w));
}

__global__ void pack_w1_bf(const float* __restrict__ w1, bf16* __restrict__ out) {
    int idx = blockIdx.x * blockDim.x + threadIdx.x;
    if (idx >= DD * KPAD) return;
    int n = idx / KPAD, j = idx % KPAD;
    out[idx] = __float2bfloat16((j < KCAT) ? w1[(size_t)n*KCAT + j] : 0.f);
}

__global__ void pack_gatein_bf(const float* __restrict__ target,
                               const float* __restrict__ attn,
                               const float* __restrict__ feat,
                               bf16* __restrict__ out) {
    int idx = blockIdx.x * blockDim.x + threadIdx.x;
    if (idx >= MQ * KPAD) return;
    int m = idx / KPAD, j = idx % KPAD;
    float v;
    if (j < DD)        v = target[(size_t)m*DD + j];
    else if (j < 2*DD) v = attn[(size_t)m*DD + (j - DD)];
    else if (j < KCAT) v = feat[(size_t)m*3 + (j - 2*DD)];
    else               v = 0.f;
    out[idx] = __float2bfloat16(v);
}

// ---------------- LayerNorm (fp32 in, bf16 out) -------------------------------
__global__ void __launch_bounds__(256) ln_bf(const float* __restrict__ x,
                                             const float* __restrict__ w,
                                             const float* __restrict__ b,
                                             bf16* __restrict__ out) {
    int row = blockIdx.x;
    int tid = threadIdx.x;
    const float4* xr = (const float4*)(x + (size_t)row * DD);
    float4 v = xr[tid];
    float s  = v.x + v.y + v.z + v.w;
    float sq = v.x*v.x + v.y*v.y + v.z*v.z + v.w*v.w;
    #pragma unroll
    for (int o = 16; o > 0; o >>= 1) {
        s  += __shfl_xor_sync(0xffffffffu, s, o);
        sq += __shfl_xor_sync(0xffffffffu, sq, o);
    }
    __shared__ float rs[8], rq[8];
    int wid = tid >> 5, lid = tid & 31;
    if (lid == 0) { rs[wid] = s; rq[wid] = sq; }
    __syncthreads();
    s = 0.f; sq = 0.f;
    #pragma unroll
    for (int i = 0; i < 8; i++) { s += rs[i]; sq += rq[i]; }
    float mean = s * (1.0f / DD);
    float var  = sq * (1.0f / DD) - mean * mean;
    float rstd = rsqrtf(var + 1e-5f);
    float4 wv = ((const float4*)w)[tid];
    float4 bv = ((const float4*)b)[tid];
    float o0 = (v.x - mean)*rstd*wv.x + bv.x;
    float o1 = (v.y - mean)*rstd*wv.y + bv.y;
    float o2 = (v.z - mean)*rstd*wv.z + bv.z;
    float o3 = (v.w - mean)*rstd*wv.w + bv.w;
    ((uint2*)(out + (size_t)row * DD))[tid] = make_uint2(packbf(o0, o1), packbf(o2, o3));
}

// ---------------- bf16 mma GEMM v2: C = A[M,K] * W[N,K]^T + bias --------------
// Block 128x128, K-chunk 64 (one SW128 row = 128B), 3-stage cp.async pipeline,
// 256 threads (8 warps, 4x2), warp tile 32x64, ldmatrix.x4 fragment loads.
// smem stage: A 16KB + W 16KB; 3 stages = 96KB dynamic.
#define GV2_SMEM (3*32768)

template<int EPI, int OUTBF>
__global__ void __launch_bounds__(256, 2) gemm_v2(const bf16* __restrict__ A,
                                                  const bf16* __restrict__ W,
                                                  const float* __restrict__ bias,
                                                  void* __restrict__ Cp,
                                                  int M, int N, int K) {
    extern __shared__ __align__(128) char sm[];
    int tid  = threadIdx.x;
    int lane = tid & 31;
    int warp = tid >> 5;
    int wm = (warp & 3) * 32;
    int wn = (warp >> 2) * 64;
    int bm = blockIdx.y * 128, bn = blockIdx.x * 128;
    int qr = lane >> 2, qc = lane & 3;
    int nk = K >> 6;

    const bf16* gA = A + (size_t)bm * K;
    const bf16* gW = W + (size_t)bn * K;

    float acc[2][8][4];
    #pragma unroll
    for (int i = 0; i < 2; i++)
        #pragma unroll
        for (int j = 0; j < 8; j++)
            #pragma unroll
            for (int t = 0; t < 4; t++) acc[i][j][t] = 0.f;

    // each thread: 8 cp16 per stage (A for i<4, W for i>=4)
    #define LOAD_STAGE(ST, KC) do {                                              \
        char* base_ = sm + (ST) * 32768;                                         \
        int k0_ = (KC) * 64;                                                     \
        _Pragma("unroll")                                                        \
        for (int i_ = 0; i_ < 8; i_++) {                                         \
            int f_ = i_ * 256 + tid;                                             \
            int m_ = f_ >> 10;                                                   \
            int r_ = (f_ & 1023) >> 3;                                           \
            int j_ = f_ & 7;                                                     \
            uint32_t off_ = (uint32_t)(r_ * 128 + ((j_ ^ (r_ & 7)) << 4));       \
            const bf16* src_ = (m_ ? gW : gA) + (size_t)r_ * K + k0_ + j_ * 8;   \
            cp16(base_ + m_ * 16384 + off_, src_);                               \
        }                                                                        \
        cp_commit();                                                             \
    } while (0)

    LOAD_STAGE(0, 0);
    LOAD_STAGE(1, 1);

    int st = 0;
    for (int kc = 0; kc < nk; kc++) {
        if (kc < nk - 1) cp_wait<1>(); else cp_wait<0>();
        __syncthreads();
        if (kc + 2 < nk) {
            int s2 = st + 2; if (s2 >= 3) s2 -= 3;
            LOAD_STAGE(s2, kc + 2);
        }

        uint32_t aB = (uint32_t)__cvta_generic_to_shared(sm + st * 32768);
        uint32_t wB = aB + 16384;

        #pragma unroll
        for (int s4 = 0; s4 < 4; s4++) {
            uint32_t a[2][4];
            #pragma unroll
            for (int mt = 0; mt < 2; mt++) {
                int r = wm + mt * 16 + (lane & 15);
                int j = s4 * 2 + (lane >> 4);
                ldm_x4(a[mt], aB + r * 128 + ((j ^ (r & 7)) << 4));
            }
            uint32_t bb[4][4];
            #pragma unroll
            for (int g = 0; g < 4; g++) {
                int r = wn + g * 16 + ((lane >> 4) << 3) + (lane & 7);
                int j = s4 * 2 + ((lane >> 3) & 1);
                ldm_x4(bb[g], wB + r * 128 + ((j ^ (r & 7)) << 4));
            }
            #pragma unroll
            for (int mt = 0; mt < 2; mt++)
                #pragma unroll
                for (int nt = 0; nt < 8; nt++)
                    mma_bf16(acc[mt][nt], a[mt], &bb[nt >> 1][(nt & 1) * 2]);
        }
        st++; if (st >= 3) st -= 3;
    }
    #undef LOAD_STAGE

    #pragma unroll
    for (int mt = 0; mt < 2; mt++) {
        int row0 = bm + wm + mt * 16 + qr;
        #pragma unroll
        for (int nt = 0; nt < 8; nt++) {
            int col = bn + wn + nt * 8 + qc * 2;
            float2 bi = *(const float2*)(bias + col);
            float v0 = acc[mt][nt][0] + bi.x;
            float v1 = acc[mt][nt][1] + bi.y;
            float v2 = acc[mt][nt][2] + bi.x;
            float v3 = acc[mt][nt][3] + bi.y;
            if (EPI == 1) {
                v0 = gelu_exact(v0); v1 = gelu_exact(v1);
                v2 = gelu_exact(v2); v3 = gelu_exact(v3);
            }
            if (OUTBF) {
                bf16* C = (bf16*)Cp;
                *(uint32_t*)(C + (size_t)row0 * N + col)       = packbf(v0, v1);
                *(uint32_t*)(C + (size_t)(row0 + 8) * N + col) = packbf(v2, v3);
            } else {
                float* C = (float*)Cp;
                *(float2*)(C + (size_t)row0 * N + col)       = make_float2(v0, v1);
                *(float2*)(C + (size_t)(row0 + 8) * N + col) = make_float2(v2, v3);
            }
        }
    }
}

// ---------------- bf16 tensor-core flash attention -----------------------------
// grid (T/64, H, B), 128 threads (4 warps). QK B-frags via ldmatrix.x4.
__global__ void __launch_bounds__(128) attn_bf(const bf16* __restrict__ Q,
                                               const bf16* __restrict__ KVb,
                                               const int* __restrict__ mask,
                                               bf16* __restrict__ O) {
    __shared__ uint32_t Ks[64][36];
    __shared__ uint32_t Vs[64][36];
    __shared__ int ms[64];

    int tid  = threadIdx.x;
    int lane = tid & 31;
    int warp = tid >> 5;
    int qr = lane >> 2, qc = lane & 3;
    int m0 = warp * 16;
    int b = blockIdx.z, h = blockIdx.y;
    int t0 = blockIdx.x * 64;

    {
        bf162 sc = __floats2bfloat162_rn(0.125f, 0.125f);
        #pragma unroll
        for (int u = 0; u < 4; u++) {
            int chunk = u * 128 + tid;
            int row = chunk >> 3, c = chunk & 7;
            uint4 t = *(const uint4*)(Q + ((size_t)(b*TT + t0 + row))*DD + h*DHH + c*8);
            bf162* p = (bf162*)&t;
            p[0] = __hmul2(p[0], sc); p[1] = __hmul2(p[1], sc);
            p[2] = __hmul2(p[2], sc); p[3] = __hmul2(p[3], sc);
            *(uint4*)&Ks[row][c*4] = t;
        }
    }
    __syncthreads();

    uint32_t qf[4][4];
    #pragma unroll
    for (int s4 = 0; s4 < 4; s4++) {
        qf[s4][0] = Ks[m0+qr  ][s4*8 + qc    ];
        qf[s4][1] = Ks[m0+qr+8][s4*8 + qc    ];
        qf[s4][2] = Ks[m0+qr  ][s4*8 + qc + 4];
        qf[s4][3] = Ks[m0+qr+8][s4*8 + qc + 4];
    }

    float o[8][4];
    #pragma unroll
    for (int nt = 0; nt < 8; nt++)
        #pragma unroll
        for (int t = 0; t < 4; t++) o[nt][t] = 0.f;
    float mrow0 = neg_inf(), mrow1 = neg_inf();
    float l0 = 0.f, l1 = 0.f;

    uint32_t ksbase = (uint32_t)__cvta_generic_to_shared(&Ks[0][0]);
    uint32_t vbase  = (uint32_t)__cvta_generic_to_shared(&Vs[lane & 15][0]);

    for (int it = 0; it < KVL/64; it++) {
        int kv0 = it * 64;
        __syncthreads();
        #pragma unroll
        for (int u = 0; u < 4; u++) {
            int chunk = u * 128 + tid;
            int row = chunk >> 3, c = chunk & 7;
            const bf16* base = KVb + ((size_t)(b*KVL + kv0 + row))*(2*DD) + h*DHH;
            *(uint4*)&Ks[row][c*4] = *(const uint4*)(base + c*8);
            *(uint4*)&Vs[row][c*4] = *(const uint4*)(base + DD + c*8);
        }
        if (tid < 64) ms[tid] = mask[(size_t)b*KVL + kv0 + tid];
        __syncthreads();

        // S = Q @ K^T; K B-frags via ldmatrix.x4 (row stride 144B)
        float s[8][4];
        #pragma unroll
        for (int nt = 0; nt < 8; nt++)
            #pragma unroll
            for (int t = 0; t < 4; t++) s[nt][t] = 0.f;
        #pragma unroll
        for (int s4 = 0; s4 < 4; s4++) {
            uint32_t kb[4][4];
            #pragma unroll
            for (int g = 0; g < 4; g++) {
                int r = g * 16 + ((lane >> 4) << 3) + (lane & 7);
                uint32_t addr = ksbase + (uint32_t)(r * 144 + s4 * 32 + (((lane >> 3) & 1) << 4));
                ldm_x4(kb[g], addr);
            }
            #pragma unroll
            for (int nt = 0; nt < 8; nt++)
                mma_bf16(s[nt], qf[s4], &kb[nt >> 1][(nt & 1) * 2]);
        }

        float tmax0 = neg_inf(), tmax1 = neg_inf();
        #pragma unroll
        for (int nt = 0; nt < 8; nt++) {
            int c0 = nt*8 + 2*qc;
            if (ms[c0] == 0)     { s[nt][0] = neg_inf(); s[nt][2] = neg_inf(); }
            if (ms[c0 + 1] == 0) { s[nt][1] = neg_inf(); s[nt][3] = neg_inf(); }
            tmax0 = fmaxf(tmax0, fmaxf(s[nt][0], s[nt][1]));
            tmax1 = fmaxf(tmax1, fmaxf(s[nt][2], s[nt][3]));
        }
        tmax0 = fmaxf(tmax0, __shfl_xor_sync(0xffffffffu, tmax0, 1));
        tmax0 = fmaxf(tmax0, __shfl_xor_sync(0xffffffffu, tmax0, 2));
        tmax1 = fmaxf(tmax1, __shfl_xor_sync(0xffffffffu, tmax1, 1));
        tmax1 = fmaxf(tmax1, __shfl_xor_sync(0xffffffffu, tmax1, 2));
        float mn0 = fmaxf(mrow0, tmax0), mb0 = fmaxf(mn0, -1e30f);
        float mn1 = fmaxf(mrow1, tmax1), mb1 = fmaxf(mn1, -1e30f);
        float corr0 = __expf(mrow0 - mb0);
        float corr1 = __expf(mrow1 - mb1);
        float ts0 = 0.f, ts1 = 0.f;
        #pragma unroll
        for (int nt = 0; nt < 8; nt++) {
            s[nt][0] = __expf(s[nt][0] - mb0);
            s[nt][1] = __expf(s[nt][1] - mb0);
            s[nt][2] = __expf(s[nt][2] - mb1);
            s[nt][3] = __expf(s[nt][3] - mb1);
            ts0 += s[nt][0] + s[nt][1];
            ts1 += s[nt][2] + s[nt][3];
        }
        ts0 += __shfl_xor_sync(0xffffffffu, ts0, 1);
        ts0 += __shfl_xor_sync(0xffffffffu, ts0, 2);
        ts1 += __shfl_xor_sync(0xffffffffu, ts1, 1);
        ts1 += __shfl_xor_sync(0xffffffffu, ts1, 2);
        l0 = l0 * corr0 + ts0;  mrow0 = mn0;
        l1 = l1 * corr1 + ts1;  mrow1 = mn1;
        #pragma unroll
        for (int nt = 0; nt < 8; nt++) {
            o[nt][0] *= corr0; o[nt][1] *= corr0;
            o[nt][2] *= corr1; o[nt][3] *= corr1;
        }

        __syncthreads();
        #pragma unroll
        for (int nt = 0; nt < 8; nt++) {
            Ks[m0+qr  ][nt*4 + qc] = packbf(s[nt][0], s[nt][1]);
            Ks[m0+qr+8][nt*4 + qc] = packbf(s[nt][2], s[nt][3]);
        }
        __syncthreads();

        #pragma unroll
        for (int s4 = 0; s4 < 4; s4++) {
            uint32_t af[4];
            af[0] = Ks[m0+qr  ][s4*8 + qc    ];
            af[1] = Ks[m0+qr+8][s4*8 + qc    ];
            af[2] = Ks[m0+qr  ][s4*8 + qc + 4];
            af[3] = Ks[m0+qr+8][s4*8 + qc + 4];
            #pragma unroll
            for (int nt = 0; nt < 8; nt++) {
                uint32_t b0, b1;
                uint32_t addr = vbase + (uint32_t)((s4*16*36 + nt*4) * 4);
                asm volatile("ldmatrix.sync.aligned.m8n8.x2.trans.shared.b16 {%0,%1}, [%2];"
                             : "=r"(b0), "=r"(b1) : "r"(addr));
                uint32_t bfr[2] = {b0, b1};
                mma_bf16(o[nt], af, bfr);
            }
        }
    }

    float i0 = 1.f / l0, i1 = 1.f / l1;
    bf16* or0 = O + ((size_t)(b*TT + t0 + m0 + qr))*DD + h*DHH;
    bf16* or1 = or0 + (size_t)8*DD;
    #pragma unroll
    for (int nt = 0; nt < 8; nt++) {
        int c0 = nt*8 + 2*qc;
        *(uint32_t*)(or0 + c0) = packbf(o[nt][0]*i0, o[nt][1]*i0);
        *(uint32_t*)(or1 + c0) = packbf(o[nt][2]*i1, o[nt][3]*i1);
    }
}

// ---------------- gate = sigmoid(h . w2 + b2) ---------------------------------
__global__ void __launch_bounds__(256) gate2_kernel(const float* __restrict__ hbuf,
                                                    const float* __restrict__ w2,
                                                    const float* __restrict__ b2,
                                                    float* __restrict__ gate) {
    int row = blockIdx.x;
    int tid = threadIdx.x;
    float4 hv = ((const float4*)(hbuf + (size_t)row * DD))[tid];
    float4 wv = ((const float4*)w2)[tid];
    float s = hv.x*wv.x + hv.y*wv.y + hv.z*wv.z + hv.w*wv.w;
    #pragma unroll
    for (int o = 16; o > 0; o >>= 1) s += __shfl_xor_sync(0xffffffffu, s, o);
    __shared__ float rs[8];
    int wid = tid >> 5, lid = tid & 31;
    if (lid == 0) rs[wid] = s;
    __syncthreads();
    if (tid == 0) {
        float tot = 0.f;
        #pragma unroll
        for (int i = 0; i < 8; i++) tot += rs[i];
        gate[row] = 1.f / (1.f + __expf(-(tot + b2[0])));
    }
}

// ---------------- fuse + residual + output LN ---------------------------------
__global__ void __launch_bounds__(256) final_kernel(const float* __restrict__ target,
                                                    const float* __restrict__ attn,
                                                    const float* __restrict__ gate,
                                                    const float* __restrict__ w,
                                                    const float* __restrict__ bparm,
                                                    float* __restrict__ out,
                                                    float* __restrict__ gate_out) {
    int row = blockIdx.x;
    int tid = threadIdx.x;
    float g = gate[row];
    float4 t4 = ((const float4*)(target + (size_t)row * DD))[tid];
    float4 a4 = ((const float4*)(attn   + (size_t)row * DD))[tid];
    float4 x;
    x.x = (2.f - g)*t4.x + g*a4.x;
    x.y = (2.f - g)*t4.y + g*a4.y;
    x.z = (2.f - g)*t4.z + g*a4.z;
    x.w = (2.f - g)*t4.w + g*a4.w;
    float s  = x.x + x.y + x.z + x.w;
    float sq = x.x*x.x + x.y*x.y + x.z*x.z + x.w*x.w;
    #pragma unroll
    for (int o = 16; o > 0; o >>= 1) {
        s  += __shfl_xor_sync(0xffffffffu, s, o);
        sq += __shfl_xor_sync(0xffffffffu, sq, o);
    }
    __shared__ float rs[8], rq[8];
    int wid = tid >> 5, lid = tid & 31;
    if (lid == 0) { rs[wid] = s; rq[wid] = sq; }
    __syncthreads();
    s = 0.f; sq = 0.f;
    #pragma unroll
    for (int i = 0; i < 8; i++) { s += rs[i]; sq += rq[i]; }
    float mean = s * (1.0f / DD);
    float var  = sq * (1.0f / DD) - mean * mean;
    float rstd = rsqrtf(var + 1e-5f);
    float4 wv = ((const float4*)w)[tid];
    float4 bv = ((const float4*)bparm)[tid];
    float4 o4;
    o4.x = (x.x - mean)*rstd*wv.x + bv.x;
    o4.y = (x.y - mean)*rstd*wv.y + bv.y;
    o4.z = (x.z - mean)*rstd*wv.z + bv.z;
    o4.w = (x.w - mean)*rstd*wv.w + bv.w;
    ((float4*)(out + (size_t)row * DD))[tid] = o4;
    if (gate_out && tid == 0) gate_out[row] = g;
}

// ---------------- launch --------------------------------------------------------
extern "C" void kernel_launch(void* const* d_in, const int* in_sizes, int n_in,
                              void* d_out, int out_size) {
    const float* target   = (const float*)d_in[0];
    const float* support  = (const float*)d_in[1];
    const float* feat     = (const float*)d_in[2];
    const int*   mask     = (const int*)d_in[3];
    const float* ln_q_w   = (const float*)d_in[4];
    const float* ln_q_b   = (const float*)d_in[5];
    const float* ln_kv_w  = (const float*)d_in[6];
    const float* ln_kv_b  = (const float*)d_in[7];
    const float* out_ln_w = (const float*)d_in[8];
    const float* out_ln_b = (const float*)d_in[9];
    const float* in_proj_w  = (const float*)d_in[10];
    const float* in_proj_b  = (const float*)d_in[11];
    const float* out_proj_w = (const float*)d_in[12];
    const float* out_proj_b = (const float*)d_in[13];
    const float* gate_w1 = (const float*)d_in[14];
    const float* gate_b1 = (const float*)d_in[15];
    const float* gate_w2 = (const float*)d_in[16];
    const float* gate_b2 = (const float*)d_in[17];

    bf16 *qin, *kvin, *q, *kv, *ctx, *gatein, *w1p, *ipw, *opw;
    float *attn, *hbuf, *gate;
    cudaGetSymbolAddress((void**)&qin,    g_qin);
    cudaGetSymbolAddress((void**)&kvin,   g_kvin);
    cudaGetSymbolAddress((void**)&q,      g_q);
    cudaGetSymbolAddress((void**)&kv,     g_kv);
    cudaGetSymbolAddress((void**)&ctx,    g_ctx);
    cudaGetSymbolAddress((void**)&attn,   g_attn);
    cudaGetSymbolAddress((void**)&gatein, g_gatein);
    cudaGetSymbolAddress((void**)&w1p,    g_w1pad);
    cudaGetSymbolAddress((void**)&ipw,    g_ipw);
    cudaGetSymbolAddress((void**)&opw,    g_opw);
    cudaGetSymbolAddress((void**)&hbuf,   g_h);
    cudaGetSymbolAddress((void**)&gate,   g_gate);

    cudaFuncSetAttribute(gemm_v2<0,1>, cudaFuncAttributeMaxDynamicSharedMemorySize, GV2_SMEM);
    cudaFuncSetAttribute(gemm_v2<0,0>, cudaFuncAttributeMaxDynamicSharedMemorySize, GV2_SMEM);
    cudaFuncSetAttribute(gemm_v2<1,0>, cudaFuncAttributeMaxDynamicSharedMemorySize, GV2_SMEM);

    // 0. weight conversions (bf16)
    f2bf<<<(3*DD*DD/4 + 255)/256, 256>>>(in_proj_w, ipw, 3*DD*DD/4);
    f2bf<<<(DD*DD/4 + 255)/256, 256>>>(out_proj_w, opw, DD*DD/4);
    pack_w1_bf<<<(DD*KPAD + 255)/256, 256>>>(gate_w1, w1p);

    // 1. input layernorms -> bf16
    ln_bf<<<MQ, 256>>>(target, ln_q_w, ln_q_b, qin);
    ln_bf<<<MKV, 256>>>(support, ln_kv_w, ln_kv_b, kvin);

    // 2. projections (q, fused kv)
    gemm_v2<0,1><<<dim3(DD/128, MQ/128), 256, GV2_SMEM>>>(qin, ipw, in_proj_b, q, MQ, DD, DD);
    gemm_v2<0,1><<<dim3((2*DD)/128, MKV/128), 256, GV2_SMEM>>>(kvin, ipw + (size_t)DD*DD,
                                                               in_proj_b + DD, kv, MKV, 2*DD, DD);

    // 3. attention
    attn_bf<<<dim3(TT/64, HH, BB), 128>>>(q, kv, mask, ctx);

    // 4. output projection (fp32 out for residual path)
    gemm_v2<0,0><<<dim3(DD/128, MQ/128), 256, GV2_SMEM>>>(ctx, opw, out_proj_b, attn, MQ, DD, DD);

    // 5. gate MLP
    pack_gatein_bf<<<(MQ*KPAD + 255)/256, 256>>>(target, attn, feat, gatein);
    gemm_v2<1,0><<<dim3(DD/128, MQ/128), 256, GV2_SMEM>>>(gatein, w1p, gate_b1, hbuf, MQ, DD, KPAD);
    gate2_kernel<<<MQ, 256>>>(hbuf, gate_w2, gate_b2, gate);

    // 6. fuse + residual + output LN (+ gate second output)
    float* gout = nullptr;
    if (out_size >= MQ*DD + MQ) gout = (float*)d_out + (size_t)MQ*DD;
    final_kernel<<<MQ, 256>>>(target, attn, gate, out_ln_w, out_ln_b, (float*)d_out, gout);
}